// round 5
// baseline (speedup 1.0000x reference)
#include <cuda_runtime.h>
#include <cuda_bf16.h>
#include <cstdint>

// Problem constants
#define BATCH   8192
#define R_DIM   8
#define PH_DIM  16
#define PAIRS   1024
#define OUT_U   8192   // PAIRS * R

#define PK_NCHUNK 32         // 32 pair chunks of 32 pairs
#define MK_TILE   64
#define MK_NTILE  (BATCH / MK_TILE)

// Deterministic partial buffer: 32 interaction chunks + X + Z
__device__ float g_partial[(PK_NCHUNK + 2) * BATCH];

typedef unsigned long long ull;

// ---- packed f32x2 helpers ---------------------------------------------------
__device__ __forceinline__ ull pack2(float lo, float hi) {
    ull r;
    asm("mov.b64 %0, {%1, %2};" : "=l"(r) : "f"(lo), "f"(hi));
    return r;
}
__device__ __forceinline__ void unpack2(ull v, float& lo, float& hi) {
    asm("mov.b64 {%0, %1}, %2;" : "=f"(lo), "=f"(hi) : "l"(v));
}
__device__ __forceinline__ ull fma2(ull a, ull b, ull c) {
    ull d;
    asm("fma.rn.f32x2 %0, %1, %2, %3;" : "=l"(d) : "l"(a), "l"(b), "l"(c));
    return d;
}
__device__ __forceinline__ uint32_t tf32_rna(float v) {
    uint32_t u;
    asm("cvt.rna.tf32.f32 %0, %1;" : "=r"(u) : "f"(v));
    return u;
}
// mma.sync m16n8k8 tf32: D = A(16x8,row) * B(8x8,col) + C  (fp32 accum)
__device__ __forceinline__ void mma_tf32(float& d0, float& d1, float& d2, float& d3,
                                         uint32_t a0, uint32_t a1, uint32_t a2, uint32_t a3,
                                         uint32_t b0, uint32_t b1) {
    asm volatile(
        "mma.sync.aligned.m16n8k8.row.col.f32.tf32.tf32.f32 "
        "{%0,%1,%2,%3}, {%4,%5,%6,%7}, {%8,%9}, {%0,%1,%2,%3};\n"
        : "+f"(d0), "+f"(d1), "+f"(d2), "+f"(d3)
        : "r"(a0), "r"(a1), "r"(a2), "r"(a3), "r"(b0), "r"(b1));
}

// ---------------------------------------------------------------------------
// Kernel 1: main-effect MLPs (32->128->64->1). blockIdx.y = part (x or z).
// ---------------------------------------------------------------------------
__global__ __launch_bounds__(128)
void mlp_kernel(const float* __restrict__ x, const float* __restrict__ z,
                const float* __restrict__ xw1, const float* __restrict__ xb1,
                const float* __restrict__ xw2, const float* __restrict__ xb2,
                const float* __restrict__ xw3, const float* __restrict__ xb3,
                const float* __restrict__ zw1, const float* __restrict__ zb1,
                const float* __restrict__ zw2, const float* __restrict__ zb2,
                const float* __restrict__ zw3, const float* __restrict__ zb3)
{
    extern __shared__ float sm[];
    float* in_sm = sm;                 // 64*32   = 2048
    float* h1_sm = sm + 2048;          // 64*128  = 8192
    float* w2_sm = sm + 10240;         // 128*64  = 8192
    float* h2_sm = sm + 18432;         // 64*68   = 4352
    float* w3_sm = sm + 22784;         // 64

    const int tid  = threadIdx.x;
    const int tile = blockIdx.x;
    const int part = blockIdx.y;
    const int g0   = tile * MK_TILE;

    const float* in = part ? z   : x;
    const float* w1 = part ? zw1 : xw1;
    const float* b1 = part ? zb1 : xb1;
    const float* w2 = part ? zw2 : xw2;
    const float* b2 = part ? zb2 : xb2;
    const float* w3 = part ? zw3 : xw3;
    const float* b3 = part ? zb3 : xb3;

    for (int idx = tid; idx < MK_TILE * 32; idx += 128)
        in_sm[idx] = in[(size_t)g0 * 32 + idx];
    for (int idx = tid; idx < 128 * 64; idx += 128)
        w2_sm[idx] = w2[idx];
    if (tid < 64) w3_sm[tid] = w3[tid];

    float wc[32];
    #pragma unroll
    for (int l = 0; l < 32; ++l) wc[l] = w1[l * 128 + tid];
    const float bc = b1[tid];

    __syncthreads();

    // ---- phase 1 ----
    for (int s = 0; s < MK_TILE; ++s) {
        float acc = bc;
        const float4* xr = (const float4*)(in_sm + s * 32);
        #pragma unroll
        for (int l4 = 0; l4 < 8; ++l4) {
            float4 v = xr[l4];
            acc = fmaf(v.x, wc[l4 * 4 + 0], acc);
            acc = fmaf(v.y, wc[l4 * 4 + 1], acc);
            acc = fmaf(v.z, wc[l4 * 4 + 2], acc);
            acc = fmaf(v.w, wc[l4 * 4 + 3], acc);
        }
        h1_sm[s * 128 + tid] = fmaxf(acc, 0.0f);
    }
    __syncthreads();

    // ---- phase 2: loop-swapped, f32x2 ----
    {
        const int oq = tid & 15;
        const int sg = tid >> 4;
        float4 bb = ((const float4*)b2)[oq];
        ull accA[8], accB[8];
        const ull bA = pack2(bb.x, bb.y);
        const ull bB = pack2(bb.z, bb.w);
        #pragma unroll
        for (int ss = 0; ss < 8; ++ss) { accA[ss] = bA; accB[ss] = bB; }

        const float4* w24   = (const float4*)w2_sm;
        const float4* hbase = (const float4*)(h1_sm + sg * 8 * 128);

        #pragma unroll 2
        for (int l4 = 0; l4 < 32; ++l4) {
            float4 wA = w24[(l4 * 4 + 0) * 16 + oq];
            float4 wB = w24[(l4 * 4 + 1) * 16 + oq];
            float4 wC = w24[(l4 * 4 + 2) * 16 + oq];
            float4 wD = w24[(l4 * 4 + 3) * 16 + oq];
            const ulonglong2 wAp = *(const ulonglong2*)&wA;
            const ulonglong2 wBp = *(const ulonglong2*)&wB;
            const ulonglong2 wCp = *(const ulonglong2*)&wC;
            const ulonglong2 wDp = *(const ulonglong2*)&wD;
            #pragma unroll
            for (int ss = 0; ss < 8; ++ss) {
                float4 hv = hbase[ss * 32 + l4];
                ull hx = pack2(hv.x, hv.x);
                ull hy = pack2(hv.y, hv.y);
                ull hz = pack2(hv.z, hv.z);
                ull hw = pack2(hv.w, hv.w);
                accA[ss] = fma2(hx, wAp.x, accA[ss]); accB[ss] = fma2(hx, wAp.y, accB[ss]);
                accA[ss] = fma2(hy, wBp.x, accA[ss]); accB[ss] = fma2(hy, wBp.y, accB[ss]);
                accA[ss] = fma2(hz, wCp.x, accA[ss]); accB[ss] = fma2(hz, wCp.y, accB[ss]);
                accA[ss] = fma2(hw, wDp.x, accA[ss]); accB[ss] = fma2(hw, wDp.y, accB[ss]);
            }
        }
        #pragma unroll
        for (int ss = 0; ss < 8; ++ss) {
            const int s = sg * 8 + ss;
            float a0, a1, a2, a3;
            unpack2(accA[ss], a0, a1);
            unpack2(accB[ss], a2, a3);
            float4 r;
            r.x = fmaxf(a0, 0.0f); r.y = fmaxf(a1, 0.0f);
            r.z = fmaxf(a2, 0.0f); r.w = fmaxf(a3, 0.0f);
            *(float4*)(h2_sm + s * 68 + oq * 4) = r;
        }
    }
    __syncthreads();

    // ---- phase 3 ----
    if (tid < MK_TILE) {
        const int s = tid;
        float acc = b3[0];
        const float* hr = h2_sm + s * 68;
        #pragma unroll
        for (int o = 0; o < 64; ++o) acc = fmaf(hr[o], w3_sm[o], acc);
        g_partial[(PK_NCHUNK + part) * BATCH + g0 + s] = acc;
    }
}

// ---------------------------------------------------------------------------
// Kernel 2: structured interaction + per-pair MLPs via mma.sync tf32.
// grid = (64 sample tiles, 32 chunks), 256 threads (8 warps x 16 samples).
// Chunk = 32 pairs sharing x-column i == chunk, k = pair index in chunk.
// Per pair, per warp:  h (SIMT, A-frag layout)  ->  2x mma m16n8k8 tf32
// (t = h @ pw1 + pb1)  ->  relu + t.pw2 epilogue (SIMT)  -> shfl reduce.
// ---------------------------------------------------------------------------
__global__ __launch_bounds__(256, 4)
void pair_kernel(const float* __restrict__ x, const float* __restrict__ z,
                 const float* __restrict__ xzw, const float* __restrict__ xzb,
                 const float* __restrict__ pw1, const float* __restrict__ pb1,
                 const float* __restrict__ pw2)
{
    __shared__ __align__(16) float x_sm[128];          // x column `chunk`
    __shared__ __align__(16) float z_sm[128 * 33];     // [sample][k], pad 33
    __shared__ __align__(16) float wq_sm[32 * 4 * 8];  // [pair][c]{wx_c,wx_c4,wz_c,wz_c4,bb_c,bb_c4,0,0}
    __shared__ __align__(16) float bf_sm[32 * 128];    // [pair][nm][lane][2] pw1 tf32 B-frags
    __shared__ __align__(16) float ep_sm[32 * 8 * 4];  // [pair][cp]{pb[2cp],pb[2cp+1],pw2[2cp],pw2[2cp+1]}

    const int tid   = threadIdx.x;
    const int tile  = blockIdx.x;    // 0..63
    const int chunk = blockIdx.y;    // 0..31
    const int g0    = tile * 128;
    const int p0    = chunk * 32;

    // ---- staging ----
    if (tid < 128) x_sm[tid] = x[(size_t)(g0 + tid) * 32 + chunk];
    for (int idx = tid; idx < 128 * 32; idx += 256) {
        int s = idx >> 5, k = idx & 31;
        z_sm[s * 33 + k] = z[(size_t)g0 * 32 + idx];
    }
    for (int idx = tid; idx < 1024; idx += 256) {
        int pr = idx >> 5, c = (idx >> 3) & 3, e = idx & 7;
        int p  = p0 + pr;
        int j  = c + ((e & 1) << 2);
        float v = 0.f;
        if (e < 2)      v = xzw[(size_t)chunk * OUT_U + p * 8 + j];
        else if (e < 4) v = xzw[(size_t)(32 + pr) * OUT_U + p * 8 + j];
        else if (e < 6) v = xzb[p * 8 + j];
        wq_sm[idx] = v;
    }
    for (int idx = tid; idx < 4096; idx += 256) {
        int pr = idx >> 7, r = idx & 127;
        int nm = r >> 6, r2 = r & 63;
        int lane = r2 >> 1, half = r2 & 1;
        int k = (lane & 3) + (half << 2);
        int n = (lane >> 2) + (nm << 3);
        float v = pw1[(size_t)(p0 + pr) * 128 + k * 16 + n];
        bf_sm[idx] = __uint_as_float(tf32_rna(v));
    }
    for (int idx = tid; idx < 1024; idx += 256) {
        int pr = idx >> 5, r = idx & 31;
        int cp = r >> 2, e = r & 3;
        int col = 2 * cp + (e & 1);
        ep_sm[idx] = (e < 2) ? pb1[(p0 + pr) * 16 + col]
                             : pw2[(p0 + pr) * 16 + col];
    }
    __syncthreads();

    const int lane = tid & 31, w = tid >> 5;
    const int g = lane >> 2, c = lane & 3;
    const int srow = w * 16 + g;

    const float xi_g  = x_sm[srow];
    const float xi_g8 = x_sm[srow + 8];
    const ull xid_g  = pack2(xi_g,  xi_g);
    const ull xid_g8 = pack2(xi_g8, xi_g8);

    float out0 = 0.f, out1 = 0.f;

    #pragma unroll 2
    for (int pl = 0; pl < 32; ++pl) {
        float zg  = z_sm[srow * 33 + pl];
        float zg8 = z_sm[(srow + 8) * 33 + pl];

        // h in A-fragment layout: thread covers (rows g, g+8) x (cols c, c+4)
        ulonglong2 wu = *(const ulonglong2*)&wq_sm[(pl * 4 + c) * 8];
        ull bbu = *(const ull*)&wq_sm[(pl * 4 + c) * 8 + 4];
        ull hg  = fma2(wu.x, xid_g,  fma2(wu.y, pack2(zg,  zg),  bbu));
        ull hg8 = fma2(wu.x, xid_g8, fma2(wu.y, pack2(zg8, zg8), bbu));
        float h0, h2, h1, h3;
        unpack2(hg,  h0, h2);   // (h[g][c], h[g][c+4])
        unpack2(hg8, h1, h3);   // (h[g+8][c], h[g+8][c+4])
        uint32_t a0 = tf32_rna(fmaxf(h0, 0.f));
        uint32_t a1 = tf32_rna(fmaxf(h1, 0.f));
        uint32_t a2 = tf32_rna(fmaxf(h2, 0.f));
        uint32_t a3 = tf32_rna(fmaxf(h3, 0.f));

        // B fragments (pw1 tf32) and bias/pw2
        uint2 bf0 = *(const uint2*)&bf_sm[pl * 128 + lane * 2];
        uint2 bf1 = *(const uint2*)&bf_sm[pl * 128 + 64 + lane * 2];
        float4 e0 = *(const float4*)&ep_sm[(pl * 8 + c) * 4];
        float4 e1 = *(const float4*)&ep_sm[(pl * 8 + c + 4) * 4];

        // t = h @ pw1 + pb1 (cols 0..7 then 8..15)
        float d0 = e0.x, d1 = e0.y, d2 = e0.x, d3 = e0.y;
        mma_tf32(d0, d1, d2, d3, a0, a1, a2, a3, bf0.x, bf0.y);
        float f0 = e1.x, f1 = e1.y, f2 = e1.x, f3 = e1.y;
        mma_tf32(f0, f1, f2, f3, a0, a1, a2, a3, bf1.x, bf1.y);

        // out += relu(t) . pw2
        out0 = fmaf(fmaxf(d0, 0.f), e0.z, out0);
        out0 = fmaf(fmaxf(d1, 0.f), e0.w, out0);
        out0 = fmaf(fmaxf(f0, 0.f), e1.z, out0);
        out0 = fmaf(fmaxf(f1, 0.f), e1.w, out0);
        out1 = fmaf(fmaxf(d2, 0.f), e0.z, out1);
        out1 = fmaf(fmaxf(d3, 0.f), e0.w, out1);
        out1 = fmaf(fmaxf(f2, 0.f), e1.z, out1);
        out1 = fmaf(fmaxf(f3, 0.f), e1.w, out1);
    }

    // reduce over the 4 threads of each row group (col partitions)
    out0 += __shfl_xor_sync(0xffffffffu, out0, 1);
    out0 += __shfl_xor_sync(0xffffffffu, out0, 2);
    out1 += __shfl_xor_sync(0xffffffffu, out1, 1);
    out1 += __shfl_xor_sync(0xffffffffu, out1, 2);
    if (c == 0) {
        g_partial[(size_t)chunk * BATCH + g0 + srow]     = out0;
        g_partial[(size_t)chunk * BATCH + g0 + srow + 8] = out1;
    }
}

// ---------------------------------------------------------------------------
// Kernel 3: deterministic final reduction over 34 partial slices.
// ---------------------------------------------------------------------------
__global__ __launch_bounds__(256)
void reduce_kernel(float* __restrict__ out)
{
    const int b = blockIdx.x * 256 + threadIdx.x;
    float s = 0.0f;
    #pragma unroll
    for (int c = 0; c < PK_NCHUNK + 2; ++c)
        s += g_partial[c * BATCH + b];
    out[b] = s;
}

// ---------------------------------------------------------------------------
extern "C" void kernel_launch(void* const* d_in, const int* in_sizes, int n_in,
                              void* d_out, int out_size)
{
    const float* x   = (const float*)d_in[0];
    const float* z   = (const float*)d_in[1];
    const float* xw1 = (const float*)d_in[2];
    const float* xb1 = (const float*)d_in[3];
    const float* xw2 = (const float*)d_in[4];
    const float* xb2 = (const float*)d_in[5];
    const float* xw3 = (const float*)d_in[6];
    const float* xb3 = (const float*)d_in[7];
    const float* zw1 = (const float*)d_in[8];
    const float* zb1 = (const float*)d_in[9];
    const float* zw2 = (const float*)d_in[10];
    const float* zb2 = (const float*)d_in[11];
    const float* zw3 = (const float*)d_in[12];
    const float* zb3 = (const float*)d_in[13];
    const float* xzw = (const float*)d_in[14];
    const float* xzb = (const float*)d_in[15];
    const float* pw1 = (const float*)d_in[16];
    const float* pb1 = (const float*)d_in[17];
    const float* pw2 = (const float*)d_in[18];
    float* out = (float*)d_out;

    static cudaStream_t s2 = nullptr;
    static cudaEvent_t  e_fork = nullptr, e_join = nullptr;
    if (s2 == nullptr) {
        cudaStreamCreateWithFlags(&s2, cudaStreamNonBlocking);
        cudaEventCreateWithFlags(&e_fork, cudaEventDisableTiming);
        cudaEventCreateWithFlags(&e_join, cudaEventDisableTiming);
    }

    const size_t smem_mlp = 22848u * sizeof(float);   // 91392 B
    cudaFuncSetAttribute(mlp_kernel, cudaFuncAttributeMaxDynamicSharedMemorySize, (int)smem_mlp);

    // fork: mlp on side stream
    cudaEventRecord(e_fork, 0);
    cudaStreamWaitEvent(s2, e_fork, 0);
    mlp_kernel<<<dim3(MK_NTILE, 2), 128, smem_mlp, s2>>>(x, z,
        xw1, xb1, xw2, xb2, xw3, xb3,
        zw1, zb1, zw2, zb2, zw3, zb3);
    cudaEventRecord(e_join, s2);

    pair_kernel<<<dim3(64, 32), 256>>>(x, z, xzw, xzb, pw1, pb1, pw2);

    cudaStreamWaitEvent(0, e_join, 0);
    reduce_kernel<<<BATCH / 256, 256>>>(out);
}

// round 6
// speedup vs baseline: 1.1261x; 1.1261x over previous
#include <cuda_runtime.h>
#include <cuda_bf16.h>

// Problem constants
#define BATCH   8192
#define R_DIM   8
#define PH_DIM  16
#define PAIRS   1024
#define OUT_U   8192   // PAIRS * R

// Pair kernel tiling
#define PK_TILE      256   // samples per CTA (2 adjacent per thread, packed)
#define PK_CHUNK     32    // pairs per CTA (one x-column per chunk)
#define PK_NCHUNK    (PAIRS / PK_CHUNK)      // 32
#define PK_NTILE     (BATCH / PK_TILE)       // 32

// MLP kernel tiling
#define MK_TILE      64
#define MK_NTILE     (BATCH / MK_TILE)       // 128

// Deterministic partial buffer: 32 interaction chunks + X + Z
__device__ float g_partial[(PK_NCHUNK + 2) * BATCH];
// Transposed inputs: [32][8192]
__device__ float g_xT[32 * BATCH];
__device__ float g_zT[32 * BATCH];

typedef unsigned long long ull;

// ---- packed f32x2 helpers ---------------------------------------------------
__device__ __forceinline__ ull pack2(float lo, float hi) {
    ull r;
    asm("mov.b64 %0, {%1, %2};" : "=l"(r) : "f"(lo), "f"(hi));
    return r;
}
__device__ __forceinline__ void unpack2(ull v, float& lo, float& hi) {
    asm("mov.b64 {%0, %1}, %2;" : "=f"(lo), "=f"(hi) : "l"(v));
}
__device__ __forceinline__ ull fma2(ull a, ull b, ull c) {
    ull d;
    asm("fma.rn.f32x2 %0, %1, %2, %3;" : "=l"(d) : "l"(a), "l"(b), "l"(c));
    return d;
}
__device__ __forceinline__ ull relu2(ull v) {
    float a, b;
    unpack2(v, a, b);
    return pack2(fmaxf(a, 0.0f), fmaxf(b, 0.0f));
}
__device__ __forceinline__ ull dup_lo(ull v) {
    float a, b; unpack2(v, a, b); return pack2(a, a);
}
__device__ __forceinline__ ull dup_hi(ull v) {
    float a, b; unpack2(v, a, b); return pack2(b, b);
}

// ---------------------------------------------------------------------------
// Kernel 0: transpose x,z [8192][32] -> [32][8192]
// ---------------------------------------------------------------------------
__global__ __launch_bounds__(256)
void transpose_kernel(const float* __restrict__ x, const float* __restrict__ z)
{
    __shared__ float tx[64 * 33];
    __shared__ float tz[64 * 33];
    const int tid = threadIdx.x;
    const int g0  = blockIdx.x * 64;

    for (int idx = tid; idx < 64 * 32; idx += 256) {
        int s = idx >> 5, c = idx & 31;
        tx[s * 33 + c] = x[(size_t)g0 * 32 + idx];
        tz[s * 33 + c] = z[(size_t)g0 * 32 + idx];
    }
    __syncthreads();
    for (int idx = tid; idx < 64 * 32; idx += 256) {
        int c = idx >> 6, s = idx & 63;
        g_xT[(size_t)c * BATCH + g0 + s] = tx[s * 33 + c];
        g_zT[(size_t)c * BATCH + g0 + s] = tz[s * 33 + c];
    }
}

// ---------------------------------------------------------------------------
// Kernel 1: main-effect MLPs (32->128->64->1). blockIdx.y = part (x or z).
// 256 threads. Phase 1: 4-way sample ILP, 2 sample-halves across warps.
// ---------------------------------------------------------------------------
__global__ __launch_bounds__(256)
void mlp_kernel(const float* __restrict__ x, const float* __restrict__ z,
                const float* __restrict__ xw1, const float* __restrict__ xb1,
                const float* __restrict__ xw2, const float* __restrict__ xb2,
                const float* __restrict__ xw3, const float* __restrict__ xb3,
                const float* __restrict__ zw1, const float* __restrict__ zb1,
                const float* __restrict__ zw2, const float* __restrict__ zb2,
                const float* __restrict__ zw3, const float* __restrict__ zb3)
{
    extern __shared__ float sm[];
    float* in_sm = sm;                 // 64*32   = 2048
    float* h1_sm = sm + 2048;          // 64*128  = 8192
    float* w2_sm = sm + 10240;         // 128*64  = 8192
    float* h2_sm = sm + 18432;         // 64*68   = 4352
    float* w3_sm = sm + 22784;         // 64

    const int tid  = threadIdx.x;
    const int tile = blockIdx.x;
    const int part = blockIdx.y;
    const int g0   = tile * MK_TILE;

    const float* in = part ? z   : x;
    const float* w1 = part ? zw1 : xw1;
    const float* b1 = part ? zb1 : xb1;
    const float* w2 = part ? zw2 : xw2;
    const float* b2 = part ? zb2 : xb2;
    const float* w3 = part ? zw3 : xw3;
    const float* b3 = part ? zb3 : xb3;

    for (int idx = tid; idx < MK_TILE * 32; idx += 256)
        in_sm[idx] = in[(size_t)g0 * 32 + idx];
    for (int idx = tid; idx < 128 * 64; idx += 256)
        w2_sm[idx] = w2[idx];
    if (tid < 64) w3_sm[tid] = w3[tid];

    const int u    = tid & 127;        // hidden unit
    const int half = tid >> 7;         // sample half (0/1)

    float wc[32];
    #pragma unroll
    for (int l = 0; l < 32; ++l) wc[l] = w1[l * 128 + u];
    const float bc = b1[u];

    __syncthreads();

    // ---- phase 1: h1[s][u] = relu(x[s]·w1col + b1), 4 samples in flight ----
    for (int s0 = half * 32; s0 < half * 32 + 32; s0 += 4) {
        float a0 = bc, a1 = bc, a2 = bc, a3 = bc;
        const float4* r0 = (const float4*)(in_sm + (s0 + 0) * 32);
        const float4* r1 = (const float4*)(in_sm + (s0 + 1) * 32);
        const float4* r2 = (const float4*)(in_sm + (s0 + 2) * 32);
        const float4* r3 = (const float4*)(in_sm + (s0 + 3) * 32);
        #pragma unroll
        for (int l4 = 0; l4 < 8; ++l4) {
            float4 v0 = r0[l4], v1 = r1[l4], v2 = r2[l4], v3 = r3[l4];
            float w0 = wc[l4 * 4 + 0], w1c = wc[l4 * 4 + 1];
            float w2c = wc[l4 * 4 + 2], w3c = wc[l4 * 4 + 3];
            a0 = fmaf(v0.x, w0, a0); a1 = fmaf(v1.x, w0, a1);
            a2 = fmaf(v2.x, w0, a2); a3 = fmaf(v3.x, w0, a3);
            a0 = fmaf(v0.y, w1c, a0); a1 = fmaf(v1.y, w1c, a1);
            a2 = fmaf(v2.y, w1c, a2); a3 = fmaf(v3.y, w1c, a3);
            a0 = fmaf(v0.z, w2c, a0); a1 = fmaf(v1.z, w2c, a1);
            a2 = fmaf(v2.z, w2c, a2); a3 = fmaf(v3.z, w2c, a3);
            a0 = fmaf(v0.w, w3c, a0); a1 = fmaf(v1.w, w3c, a1);
            a2 = fmaf(v2.w, w3c, a2); a3 = fmaf(v3.w, w3c, a3);
        }
        h1_sm[(s0 + 0) * 128 + u] = fmaxf(a0, 0.0f);
        h1_sm[(s0 + 1) * 128 + u] = fmaxf(a1, 0.0f);
        h1_sm[(s0 + 2) * 128 + u] = fmaxf(a2, 0.0f);
        h1_sm[(s0 + 3) * 128 + u] = fmaxf(a3, 0.0f);
    }
    __syncthreads();

    // ---- phase 2: h2 = relu(h1 @ w2 + b2); 4 samples/thread, f32x2 ----
    {
        const int oq = tid & 15;           // outputs 4*oq .. 4*oq+3
        const int sg = tid >> 4;           // samples sg*4 .. sg*4+3
        float4 bb = ((const float4*)b2)[oq];
        ull accA[4], accB[4];
        const ull bA = pack2(bb.x, bb.y);
        const ull bB = pack2(bb.z, bb.w);
        #pragma unroll
        for (int ss = 0; ss < 4; ++ss) { accA[ss] = bA; accB[ss] = bB; }

        const float4* w24   = (const float4*)w2_sm;
        const float4* hbase = (const float4*)(h1_sm + sg * 4 * 128);

        #pragma unroll 4
        for (int l4 = 0; l4 < 32; ++l4) {
            float4 wA = w24[(l4 * 4 + 0) * 16 + oq];
            float4 wB = w24[(l4 * 4 + 1) * 16 + oq];
            float4 wC = w24[(l4 * 4 + 2) * 16 + oq];
            float4 wD = w24[(l4 * 4 + 3) * 16 + oq];
            const ulonglong2 wAp = *(const ulonglong2*)&wA;
            const ulonglong2 wBp = *(const ulonglong2*)&wB;
            const ulonglong2 wCp = *(const ulonglong2*)&wC;
            const ulonglong2 wDp = *(const ulonglong2*)&wD;
            #pragma unroll
            for (int ss = 0; ss < 4; ++ss) {
                float4 hv = hbase[ss * 32 + l4];
                ull hx = pack2(hv.x, hv.x);
                ull hy = pack2(hv.y, hv.y);
                ull hz = pack2(hv.z, hv.z);
                ull hw = pack2(hv.w, hv.w);
                accA[ss] = fma2(hx, wAp.x, accA[ss]); accB[ss] = fma2(hx, wAp.y, accB[ss]);
                accA[ss] = fma2(hy, wBp.x, accA[ss]); accB[ss] = fma2(hy, wBp.y, accB[ss]);
                accA[ss] = fma2(hz, wCp.x, accA[ss]); accB[ss] = fma2(hz, wCp.y, accB[ss]);
                accA[ss] = fma2(hw, wDp.x, accA[ss]); accB[ss] = fma2(hw, wDp.y, accB[ss]);
            }
        }
        #pragma unroll
        for (int ss = 0; ss < 4; ++ss) {
            const int s = sg * 4 + ss;
            float a0, a1, a2, a3;
            unpack2(accA[ss], a0, a1);
            unpack2(accB[ss], a2, a3);
            float4 r;
            r.x = fmaxf(a0, 0.0f); r.y = fmaxf(a1, 0.0f);
            r.z = fmaxf(a2, 0.0f); r.w = fmaxf(a3, 0.0f);
            *(float4*)(h2_sm + s * 68 + oq * 4) = r;
        }
    }
    __syncthreads();

    // ---- phase 3: out = h2 · w3 + b3, 4 threads per sample + shfl ----
    {
        const int s = tid >> 2, q = tid & 3;
        const float4* hr = (const float4*)(h2_sm + s * 68 + q * 16);
        const float4* wr = (const float4*)(w3_sm + q * 16);
        float acc = 0.0f;
        #pragma unroll
        for (int i = 0; i < 4; ++i) {
            float4 h = hr[i], w = wr[i];
            acc = fmaf(h.x, w.x, acc);
            acc = fmaf(h.y, w.y, acc);
            acc = fmaf(h.z, w.z, acc);
            acc = fmaf(h.w, w.w, acc);
        }
        acc += __shfl_xor_sync(0xffffffffu, acc, 1);
        acc += __shfl_xor_sync(0xffffffffu, acc, 2);
        if (q == 0)
            g_partial[(PK_NCHUNK + part) * BATCH + g0 + s] = acc + b3[0];
    }
}

// ---------------------------------------------------------------------------
// Kernel 2: structured interaction + per-pair MLPs, fully f32x2-packed.
// (round-4 proven version)
// ---------------------------------------------------------------------------
__global__ __launch_bounds__(128, 4)
void pair_kernel(const float* __restrict__ xzw, const float* __restrict__ xzb,
                 const float* __restrict__ pw1, const float* __restrict__ pb1,
                 const float* __restrict__ pw2)
{
    __shared__ __align__(16) float sm[6656];   // 26624 B
    float* wxd_sm = sm;            // 512 (32 pairs x 8 x dup2)
    float* wzd_sm = sm + 512;      // 512
    float* bbd_sm = sm + 1024;     // 512
    float* pw1_sm = sm + 1536;     // 4096
    float* pb1_sm = sm + 5632;     // 512
    float* pw2_sm = sm + 6144;     // 512

    const int tid   = threadIdx.x;
    const int tile  = blockIdx.x;
    const int chunk = blockIdx.y;
    const int g0    = tile * PK_TILE;
    const int p0    = chunk * PK_CHUNK;

    // stage duplicated h-stage weights
    for (int idx = tid; idx < PK_CHUNK * R_DIM; idx += 128) {
        int col = p0 * R_DIM + idx;
        int k   = idx >> 3;                 // pair index within chunk == z index
        float wx = xzw[(size_t)chunk * OUT_U + col];
        float wz = xzw[(size_t)(32 + k) * OUT_U + col];
        float bb = xzb[col];
        wxd_sm[2 * idx] = wx; wxd_sm[2 * idx + 1] = wx;
        wzd_sm[2 * idx] = wz; wzd_sm[2 * idx + 1] = wz;
        bbd_sm[2 * idx] = bb; bbd_sm[2 * idx + 1] = bb;
    }
    for (int idx = tid; idx < PK_CHUNK * R_DIM * PH_DIM; idx += 128)
        pw1_sm[idx] = pw1[(size_t)p0 * R_DIM * PH_DIM + idx];
    for (int idx = tid; idx < PK_CHUNK * PH_DIM; idx += 128) {
        pb1_sm[idx] = pb1[(size_t)p0 * PH_DIM + idx];
        pw2_sm[idx] = pw2[(size_t)p0 * PH_DIM + idx];
    }

    // packed sample pair (s0 = g0 + 2*tid, s1 = s0 + 1)
    const float2 xi2 = ((const float2*)(g_xT + (size_t)chunk * BATCH + g0))[tid];
    const ull xi = pack2(xi2.x, xi2.y);
    const float2* zT2 = (const float2*)(g_zT + g0) + tid;  // column stride = 4096 float2

    __syncthreads();

    const ulonglong2* wxd2 = (const ulonglong2*)wxd_sm;   // 4 per pair
    const ulonglong2* wzd2 = (const ulonglong2*)wzd_sm;
    const ulonglong2* bbd2 = (const ulonglong2*)bbd_sm;
    const ulonglong2* pw1v = (const ulonglong2*)pw1_sm;   // 4 per (pair,j)
    const ulonglong2* pb1v = (const ulonglong2*)pb1_sm;   // 4 per pair
    const ulonglong2* pw2v = (const ulonglong2*)pw2_sm;   // 4 per pair

    ull o0[4], o1[4];
    #pragma unroll
    for (int k = 0; k < 4; ++k) { o0[k] = 0ull; o1[k] = 0ull; }

    float2 zkf = zT2[0];

    #pragma unroll 1
    for (int pl = 0; pl < PK_CHUNK; ++pl) {
        float2 zkn = zT2[((pl + 1) & 31) * (BATCH / 2)];   // prefetch next column
        const ull zk = pack2(zkf.x, zkf.y);

        ulonglong2 wxA = wxd2[pl * 4 + 0], wxB = wxd2[pl * 4 + 1];
        ulonglong2 wxC = wxd2[pl * 4 + 2], wxD = wxd2[pl * 4 + 3];
        ulonglong2 wzA = wzd2[pl * 4 + 0], wzB = wzd2[pl * 4 + 1];
        ulonglong2 wzC = wzd2[pl * 4 + 2], wzD = wzd2[pl * 4 + 3];
        ulonglong2 bbA = bbd2[pl * 4 + 0], bbB = bbd2[pl * 4 + 1];
        ulonglong2 bbC = bbd2[pl * 4 + 2], bbD = bbd2[pl * 4 + 3];
        ull h[8];
        h[0] = relu2(fma2(wxA.x, xi, fma2(wzA.x, zk, bbA.x)));
        h[1] = relu2(fma2(wxA.y, xi, fma2(wzA.y, zk, bbA.y)));
        h[2] = relu2(fma2(wxB.x, xi, fma2(wzB.x, zk, bbB.x)));
        h[3] = relu2(fma2(wxB.y, xi, fma2(wzB.y, zk, bbB.y)));
        h[4] = relu2(fma2(wxC.x, xi, fma2(wzC.x, zk, bbC.x)));
        h[5] = relu2(fma2(wxC.y, xi, fma2(wzC.y, zk, bbC.y)));
        h[6] = relu2(fma2(wxD.x, xi, fma2(wzD.x, zk, bbD.x)));
        h[7] = relu2(fma2(wxD.y, xi, fma2(wzD.y, zk, bbD.y)));

        ull t0[8], t1[8];
        {
            ulonglong2 q;
            q = pb1v[pl * 4 + 0]; t0[0] = q.x; t0[1] = q.y; t1[0] = q.x; t1[1] = q.y;
            q = pb1v[pl * 4 + 1]; t0[2] = q.x; t0[3] = q.y; t1[2] = q.x; t1[3] = q.y;
            q = pb1v[pl * 4 + 2]; t0[4] = q.x; t0[5] = q.y; t1[4] = q.x; t1[5] = q.y;
            q = pb1v[pl * 4 + 3]; t0[6] = q.x; t0[7] = q.y; t1[6] = q.x; t1[7] = q.y;
        }

        #pragma unroll
        for (int j = 0; j < 8; ++j) {
            const ulonglong2* wv = pw1v + (pl * 8 + j) * 4;
            ulonglong2 wA = wv[0], wB = wv[1], wC = wv[2], wD = wv[3];
            ull hv0 = dup_lo(h[j]);
            ull hv1 = dup_hi(h[j]);
            t0[0] = fma2(hv0, wA.x, t0[0]); t0[1] = fma2(hv0, wA.y, t0[1]);
            t0[2] = fma2(hv0, wB.x, t0[2]); t0[3] = fma2(hv0, wB.y, t0[3]);
            t0[4] = fma2(hv0, wC.x, t0[4]); t0[5] = fma2(hv0, wC.y, t0[5]);
            t0[6] = fma2(hv0, wD.x, t0[6]); t0[7] = fma2(hv0, wD.y, t0[7]);
            t1[0] = fma2(hv1, wA.x, t1[0]); t1[1] = fma2(hv1, wA.y, t1[1]);
            t1[2] = fma2(hv1, wB.x, t1[2]); t1[3] = fma2(hv1, wB.y, t1[3]);
            t1[4] = fma2(hv1, wC.x, t1[4]); t1[5] = fma2(hv1, wC.y, t1[5]);
            t1[6] = fma2(hv1, wD.x, t1[6]); t1[7] = fma2(hv1, wD.y, t1[7]);
        }

        ulonglong2 qA = pw2v[pl * 4 + 0], qB = pw2v[pl * 4 + 1];
        ulonglong2 qC = pw2v[pl * 4 + 2], qD = pw2v[pl * 4 + 3];
        o0[0] = fma2(relu2(t0[0]), qA.x, o0[0]);
        o0[1] = fma2(relu2(t0[1]), qA.y, o0[1]);
        o0[2] = fma2(relu2(t0[2]), qB.x, o0[2]);
        o0[3] = fma2(relu2(t0[3]), qB.y, o0[3]);
        o0[0] = fma2(relu2(t0[4]), qC.x, o0[0]);
        o0[1] = fma2(relu2(t0[5]), qC.y, o0[1]);
        o0[2] = fma2(relu2(t0[6]), qD.x, o0[2]);
        o0[3] = fma2(relu2(t0[7]), qD.y, o0[3]);
        o1[0] = fma2(relu2(t1[0]), qA.x, o1[0]);
        o1[1] = fma2(relu2(t1[1]), qA.y, o1[1]);
        o1[2] = fma2(relu2(t1[2]), qB.x, o1[2]);
        o1[3] = fma2(relu2(t1[3]), qB.y, o1[3]);
        o1[0] = fma2(relu2(t1[4]), qC.x, o1[0]);
        o1[1] = fma2(relu2(t1[5]), qC.y, o1[1]);
        o1[2] = fma2(relu2(t1[6]), qD.x, o1[2]);
        o1[3] = fma2(relu2(t1[7]), qD.y, o1[3]);

        zkf = zkn;
    }

    // horizontal sums (fixed order -> deterministic)
    float a, b, s0, s1;
    unpack2(o0[0], a, b); s0 = a + b;
    unpack2(o0[1], a, b); s0 += a + b;
    unpack2(o0[2], a, b); s0 += a + b;
    unpack2(o0[3], a, b); s0 += a + b;
    unpack2(o1[0], a, b); s1 = a + b;
    unpack2(o1[1], a, b); s1 += a + b;
    unpack2(o1[2], a, b); s1 += a + b;
    unpack2(o1[3], a, b); s1 += a + b;

    float2 o2; o2.x = s0; o2.y = s1;
    ((float2*)(g_partial + (size_t)chunk * BATCH + g0))[tid] = o2;
}

// ---------------------------------------------------------------------------
// Kernel 3: deterministic final reduction over 34 partial slices.
// ---------------------------------------------------------------------------
__global__ __launch_bounds__(128)
void reduce_kernel(float* __restrict__ out)
{
    const int b = blockIdx.x * 128 + threadIdx.x;
    float s = 0.0f;
    #pragma unroll
    for (int c = 0; c < PK_NCHUNK + 2; ++c)
        s += g_partial[c * BATCH + b];
    out[b] = s;
}

// ---------------------------------------------------------------------------
extern "C" void kernel_launch(void* const* d_in, const int* in_sizes, int n_in,
                              void* d_out, int out_size)
{
    const float* x   = (const float*)d_in[0];
    const float* z   = (const float*)d_in[1];
    const float* xw1 = (const float*)d_in[2];
    const float* xb1 = (const float*)d_in[3];
    const float* xw2 = (const float*)d_in[4];
    const float* xb2 = (const float*)d_in[5];
    const float* xw3 = (const float*)d_in[6];
    const float* xb3 = (const float*)d_in[7];
    const float* zw1 = (const float*)d_in[8];
    const float* zb1 = (const float*)d_in[9];
    const float* zw2 = (const float*)d_in[10];
    const float* zb2 = (const float*)d_in[11];
    const float* zw3 = (const float*)d_in[12];
    const float* zb3 = (const float*)d_in[13];
    const float* xzw = (const float*)d_in[14];
    const float* xzb = (const float*)d_in[15];
    const float* pw1 = (const float*)d_in[16];
    const float* pb1 = (const float*)d_in[17];
    const float* pw2 = (const float*)d_in[18];
    float* out = (float*)d_out;

    static cudaStream_t s2 = nullptr;
    static cudaEvent_t  e_fork = nullptr, e_join = nullptr;
    if (s2 == nullptr) {
        cudaStreamCreateWithFlags(&s2, cudaStreamNonBlocking);
        cudaEventCreateWithFlags(&e_fork, cudaEventDisableTiming);
        cudaEventCreateWithFlags(&e_join, cudaEventDisableTiming);
    }

    const size_t smem_mlp = 22848u * sizeof(float);   // 91392 B
    cudaFuncSetAttribute(mlp_kernel, cudaFuncAttributeMaxDynamicSharedMemorySize, (int)smem_mlp);

    // fork: mlp on side stream, overlapped with transpose+pair on main stream
    cudaEventRecord(e_fork, 0);
    cudaStreamWaitEvent(s2, e_fork, 0);
    mlp_kernel<<<dim3(MK_NTILE, 2), 256, smem_mlp, s2>>>(x, z,
        xw1, xb1, xw2, xb2, xw3, xb3,
        zw1, zb1, zw2, zb2, zw3, zb3);
    cudaEventRecord(e_join, s2);

    transpose_kernel<<<BATCH / 64, 256>>>(x, z);
    pair_kernel<<<dim3(PK_NTILE, PK_NCHUNK), 128>>>(xzw, xzb, pw1, pb1, pw2);

    cudaStreamWaitEvent(0, e_join, 0);
    reduce_kernel<<<BATCH / 128, 128>>>(out);
}

// round 7
// speedup vs baseline: 1.3182x; 1.1706x over previous
#include <cuda_runtime.h>
#include <cuda_bf16.h>
#include <cstdint>

// Problem constants
#define BATCH   8192
#define R_DIM   8
#define PH_DIM  16
#define PAIRS   1024
#define OUT_U   8192   // PAIRS * R

#define PK_NCHUNK 32         // 32 pair chunks of 32 pairs
#define MK_TILE   64
#define MK_NTILE  (BATCH / MK_TILE)

// Deterministic partial buffer: 32 interaction chunks + X + Z
__device__ float g_partial[(PK_NCHUNK + 2) * BATCH];
// Transposed inputs: [32][8192]
__device__ float g_xT[32 * BATCH];
__device__ float g_zT[32 * BATCH];

typedef unsigned long long ull;

// ---- packed f32x2 helpers ---------------------------------------------------
__device__ __forceinline__ ull pack2(float lo, float hi) {
    ull r;
    asm("mov.b64 %0, {%1, %2};" : "=l"(r) : "f"(lo), "f"(hi));
    return r;
}
__device__ __forceinline__ void unpack2(ull v, float& lo, float& hi) {
    asm("mov.b64 {%0, %1}, %2;" : "=f"(lo), "=f"(hi) : "l"(v));
}
__device__ __forceinline__ ull fma2(ull a, ull b, ull c) {
    ull d;
    asm("fma.rn.f32x2 %0, %1, %2, %3;" : "=l"(d) : "l"(a), "l"(b), "l"(c));
    return d;
}
__device__ __forceinline__ uint32_t tf32_rna(float v) {
    uint32_t u;
    asm("cvt.rna.tf32.f32 %0, %1;" : "=r"(u) : "f"(v));
    return u;
}
// mma.sync m16n8k8 tf32: D = A(16x8,row) * B(8x8,col) + C  (fp32 accum)
__device__ __forceinline__ void mma_tf32(float& d0, float& d1, float& d2, float& d3,
                                         uint32_t a0, uint32_t a1, uint32_t a2, uint32_t a3,
                                         uint32_t b0, uint32_t b1) {
    asm volatile(
        "mma.sync.aligned.m16n8k8.row.col.f32.tf32.tf32.f32 "
        "{%0,%1,%2,%3}, {%4,%5,%6,%7}, {%8,%9}, {%0,%1,%2,%3};\n"
        : "+f"(d0), "+f"(d1), "+f"(d2), "+f"(d3)
        : "r"(a0), "r"(a1), "r"(a2), "r"(a3), "r"(b0), "r"(b1));
}

// ---------------------------------------------------------------------------
// Kernel 0: transpose x,z [8192][32] -> [32][8192]
// ---------------------------------------------------------------------------
__global__ __launch_bounds__(256)
void transpose_kernel(const float* __restrict__ x, const float* __restrict__ z)
{
    __shared__ float tx[64 * 33];
    __shared__ float tz[64 * 33];
    const int tid = threadIdx.x;
    const int g0  = blockIdx.x * 64;

    for (int idx = tid; idx < 64 * 32; idx += 256) {
        int s = idx >> 5, c = idx & 31;
        tx[s * 33 + c] = x[(size_t)g0 * 32 + idx];
        tz[s * 33 + c] = z[(size_t)g0 * 32 + idx];
    }
    __syncthreads();
    for (int idx = tid; idx < 64 * 32; idx += 256) {
        int c = idx >> 6, s = idx & 63;
        g_xT[(size_t)c * BATCH + g0 + s] = tx[s * 33 + c];
        g_zT[(size_t)c * BATCH + g0 + s] = tz[s * 33 + c];
    }
}

// ---------------------------------------------------------------------------
// Kernel 1: main-effect MLPs (32->128->64->1). blockIdx.y = part (x or z).
// 256 threads; proven round-6 version.
// ---------------------------------------------------------------------------
__global__ __launch_bounds__(256)
void mlp_kernel(const float* __restrict__ x, const float* __restrict__ z,
                const float* __restrict__ xw1, const float* __restrict__ xb1,
                const float* __restrict__ xw2, const float* __restrict__ xb2,
                const float* __restrict__ xw3, const float* __restrict__ xb3,
                const float* __restrict__ zw1, const float* __restrict__ zb1,
                const float* __restrict__ zw2, const float* __restrict__ zb2,
                const float* __restrict__ zw3, const float* __restrict__ zb3)
{
    extern __shared__ float sm[];
    float* in_sm = sm;                 // 64*32   = 2048
    float* h1_sm = sm + 2048;          // 64*128  = 8192
    float* w2_sm = sm + 10240;         // 128*64  = 8192
    float* h2_sm = sm + 18432;         // 64*68   = 4352
    float* w3_sm = sm + 22784;         // 64

    const int tid  = threadIdx.x;
    const int tile = blockIdx.x;
    const int part = blockIdx.y;
    const int g0   = tile * MK_TILE;

    const float* in = part ? z   : x;
    const float* w1 = part ? zw1 : xw1;
    const float* b1 = part ? zb1 : xb1;
    const float* w2 = part ? zw2 : xw2;
    const float* b2 = part ? zb2 : xb2;
    const float* w3 = part ? zw3 : xw3;
    const float* b3 = part ? zb3 : xb3;

    for (int idx = tid; idx < MK_TILE * 32; idx += 256)
        in_sm[idx] = in[(size_t)g0 * 32 + idx];
    for (int idx = tid; idx < 128 * 64; idx += 256)
        w2_sm[idx] = w2[idx];
    if (tid < 64) w3_sm[tid] = w3[tid];

    const int u    = tid & 127;        // hidden unit
    const int half = tid >> 7;         // sample half (0/1)

    float wc[32];
    #pragma unroll
    for (int l = 0; l < 32; ++l) wc[l] = w1[l * 128 + u];
    const float bc = b1[u];

    __syncthreads();

    // ---- phase 1: 4 samples in flight ----
    for (int s0 = half * 32; s0 < half * 32 + 32; s0 += 4) {
        float a0 = bc, a1 = bc, a2 = bc, a3 = bc;
        const float4* r0 = (const float4*)(in_sm + (s0 + 0) * 32);
        const float4* r1 = (const float4*)(in_sm + (s0 + 1) * 32);
        const float4* r2 = (const float4*)(in_sm + (s0 + 2) * 32);
        const float4* r3 = (const float4*)(in_sm + (s0 + 3) * 32);
        #pragma unroll
        for (int l4 = 0; l4 < 8; ++l4) {
            float4 v0 = r0[l4], v1 = r1[l4], v2 = r2[l4], v3 = r3[l4];
            float w0 = wc[l4 * 4 + 0], w1c = wc[l4 * 4 + 1];
            float w2c = wc[l4 * 4 + 2], w3c = wc[l4 * 4 + 3];
            a0 = fmaf(v0.x, w0, a0); a1 = fmaf(v1.x, w0, a1);
            a2 = fmaf(v2.x, w0, a2); a3 = fmaf(v3.x, w0, a3);
            a0 = fmaf(v0.y, w1c, a0); a1 = fmaf(v1.y, w1c, a1);
            a2 = fmaf(v2.y, w1c, a2); a3 = fmaf(v3.y, w1c, a3);
            a0 = fmaf(v0.z, w2c, a0); a1 = fmaf(v1.z, w2c, a1);
            a2 = fmaf(v2.z, w2c, a2); a3 = fmaf(v3.z, w2c, a3);
            a0 = fmaf(v0.w, w3c, a0); a1 = fmaf(v1.w, w3c, a1);
            a2 = fmaf(v2.w, w3c, a2); a3 = fmaf(v3.w, w3c, a3);
        }
        h1_sm[(s0 + 0) * 128 + u] = fmaxf(a0, 0.0f);
        h1_sm[(s0 + 1) * 128 + u] = fmaxf(a1, 0.0f);
        h1_sm[(s0 + 2) * 128 + u] = fmaxf(a2, 0.0f);
        h1_sm[(s0 + 3) * 128 + u] = fmaxf(a3, 0.0f);
    }
    __syncthreads();

    // ---- phase 2: 4 samples/thread, f32x2 ----
    {
        const int oq = tid & 15;
        const int sg = tid >> 4;
        float4 bb = ((const float4*)b2)[oq];
        ull accA[4], accB[4];
        const ull bA = pack2(bb.x, bb.y);
        const ull bB = pack2(bb.z, bb.w);
        #pragma unroll
        for (int ss = 0; ss < 4; ++ss) { accA[ss] = bA; accB[ss] = bB; }

        const float4* w24   = (const float4*)w2_sm;
        const float4* hbase = (const float4*)(h1_sm + sg * 4 * 128);

        #pragma unroll 4
        for (int l4 = 0; l4 < 32; ++l4) {
            float4 wA = w24[(l4 * 4 + 0) * 16 + oq];
            float4 wB = w24[(l4 * 4 + 1) * 16 + oq];
            float4 wC = w24[(l4 * 4 + 2) * 16 + oq];
            float4 wD = w24[(l4 * 4 + 3) * 16 + oq];
            const ulonglong2 wAp = *(const ulonglong2*)&wA;
            const ulonglong2 wBp = *(const ulonglong2*)&wB;
            const ulonglong2 wCp = *(const ulonglong2*)&wC;
            const ulonglong2 wDp = *(const ulonglong2*)&wD;
            #pragma unroll
            for (int ss = 0; ss < 4; ++ss) {
                float4 hv = hbase[ss * 32 + l4];
                ull hx = pack2(hv.x, hv.x);
                ull hy = pack2(hv.y, hv.y);
                ull hz = pack2(hv.z, hv.z);
                ull hw = pack2(hv.w, hv.w);
                accA[ss] = fma2(hx, wAp.x, accA[ss]); accB[ss] = fma2(hx, wAp.y, accB[ss]);
                accA[ss] = fma2(hy, wBp.x, accA[ss]); accB[ss] = fma2(hy, wBp.y, accB[ss]);
                accA[ss] = fma2(hz, wCp.x, accA[ss]); accB[ss] = fma2(hz, wCp.y, accB[ss]);
                accA[ss] = fma2(hw, wDp.x, accA[ss]); accB[ss] = fma2(hw, wDp.y, accB[ss]);
            }
        }
        #pragma unroll
        for (int ss = 0; ss < 4; ++ss) {
            const int s = sg * 4 + ss;
            float a0, a1, a2, a3;
            unpack2(accA[ss], a0, a1);
            unpack2(accB[ss], a2, a3);
            float4 r;
            r.x = fmaxf(a0, 0.0f); r.y = fmaxf(a1, 0.0f);
            r.z = fmaxf(a2, 0.0f); r.w = fmaxf(a3, 0.0f);
            *(float4*)(h2_sm + s * 68 + oq * 4) = r;
        }
    }
    __syncthreads();

    // ---- phase 3 ----
    {
        const int s = tid >> 2, q = tid & 3;
        const float4* hr = (const float4*)(h2_sm + s * 68 + q * 16);
        const float4* wr = (const float4*)(w3_sm + q * 16);
        float acc = 0.0f;
        #pragma unroll
        for (int i = 0; i < 4; ++i) {
            float4 h = hr[i], w = wr[i];
            acc = fmaf(h.x, w.x, acc);
            acc = fmaf(h.y, w.y, acc);
            acc = fmaf(h.z, w.z, acc);
            acc = fmaf(h.w, w.w, acc);
        }
        acc += __shfl_xor_sync(0xffffffffu, acc, 1);
        acc += __shfl_xor_sync(0xffffffffu, acc, 2);
        if (q == 0)
            g_partial[(PK_NCHUNK + part) * BATCH + g0 + s] = acc + b3[0];
    }
}

// ---------------------------------------------------------------------------
// Kernel 2: structured interaction + per-pair MLPs via tf32 mma, pairs-outer.
// grid = (16 sample tiles of 512, 32 chunks), 256 threads = 8 warps.
// Warp owns 64 samples (4 m16 subtiles). Per pair: B-frags (pw1), epilogue
// (pb1/pw2) and h-weights loaded ONCE into regs, reused across 4 subtiles.
// Fragment layouts identical to the verified round-5 kernel.
// ---------------------------------------------------------------------------
__global__ __launch_bounds__(256, 3)
void pair_kernel(const float* __restrict__ xzw, const float* __restrict__ xzb,
                 const float* __restrict__ pw1, const float* __restrict__ pb1,
                 const float* __restrict__ pw2)
{
    __shared__ __align__(16) float x_sm[512];          // x column `chunk`
    __shared__ __align__(16) float wq_sm[1024];        // [pair][c]{wx_c,wx_c4,wz_c,wz_c4,bb_c,bb_c4,0,0}
    __shared__ __align__(16) float bf_sm[4096];        // pw1 tf32 B-frags
    __shared__ __align__(16) float ep_sm[1024];        // [pair][cp]{pb,pb,pw2,pw2}

    const int tid   = threadIdx.x;
    const int tile  = blockIdx.x;    // 0..15
    const int chunk = blockIdx.y;    // 0..31
    const int g0    = tile * 512;
    const int p0    = chunk * 32;

    // ---- staging ----
    for (int idx = tid; idx < 512; idx += 256)
        x_sm[idx] = g_xT[(size_t)chunk * BATCH + g0 + idx];
    for (int idx = tid; idx < 1024; idx += 256) {
        int pr = idx >> 5, c = (idx >> 3) & 3, e = idx & 7;
        int p  = p0 + pr;
        int j  = c + ((e & 1) << 2);
        float v = 0.f;
        if (e < 2)      v = xzw[(size_t)chunk * OUT_U + p * 8 + j];
        else if (e < 4) v = xzw[(size_t)(32 + pr) * OUT_U + p * 8 + j];
        else if (e < 6) v = xzb[p * 8 + j];
        wq_sm[idx] = v;
    }
    for (int idx = tid; idx < 4096; idx += 256) {
        int pr = idx >> 7, r = idx & 127;
        int nm = r >> 6, r2 = r & 63;
        int ln = r2 >> 1, half = r2 & 1;
        int k = (ln & 3) + (half << 2);
        int n = (ln >> 2) + (nm << 3);
        bf_sm[idx] = __uint_as_float(tf32_rna(pw1[(size_t)(p0 + pr) * 128 + k * 16 + n]));
    }
    for (int idx = tid; idx < 1024; idx += 256) {
        int pr = idx >> 5, r = idx & 31;
        int cp = r >> 2, e = r & 3;
        int col = 2 * cp + (e & 1);
        ep_sm[idx] = (e < 2) ? pb1[(p0 + pr) * 16 + col]
                             : pw2[(p0 + pr) * 16 + col];
    }
    __syncthreads();

    const int lane = tid & 31, w = tid >> 5;
    const int g = lane >> 2, c = lane & 3;
    const int sbase = w * 64;                  // warp's sample base within tile

    // x duplicated pairs, once per kernel
    ull xid[8];
    #pragma unroll
    for (int sub = 0; sub < 4; ++sub) {
        float xa = x_sm[sbase + sub * 16 + g];
        float xb = x_sm[sbase + sub * 16 + g + 8];
        xid[2 * sub]     = pack2(xa, xa);
        xid[2 * sub + 1] = pack2(xb, xb);
    }

    float outv[8];
    #pragma unroll
    for (int i = 0; i < 8; ++i) outv[i] = 0.f;

    const float* zT = g_zT + g0;

    #pragma unroll 1
    for (int pl = 0; pl < 32; ++pl) {
        // per-pair registers (reused across 4 subtiles)
        ulonglong2 wu = *(const ulonglong2*)&wq_sm[(pl * 4 + c) * 8];
        ull bbu = *(const ull*)&wq_sm[(pl * 4 + c) * 8 + 4];
        uint2 bf0 = *(const uint2*)&bf_sm[pl * 128 + lane * 2];
        uint2 bf1 = *(const uint2*)&bf_sm[pl * 128 + 64 + lane * 2];
        float4 e0 = *(const float4*)&ep_sm[(pl * 8 + c) * 4];
        float4 e1 = *(const float4*)&ep_sm[(pl * 8 + c + 4) * 4];
        const float* zcol = zT + (size_t)pl * BATCH;

        #pragma unroll
        for (int sub = 0; sub < 4; ++sub) {
            const int srow = sbase + sub * 16 + g;
            float zg  = zcol[srow];
            float zg8 = zcol[srow + 8];

            // h in A-frag layout: rows {g, g+8} x cols {c, c+4}
            ull hg  = fma2(wu.x, xid[2 * sub],     fma2(wu.y, pack2(zg,  zg),  bbu));
            ull hg8 = fma2(wu.x, xid[2 * sub + 1], fma2(wu.y, pack2(zg8, zg8), bbu));
            float h0, h2, h1, h3;
            unpack2(hg,  h0, h2);
            unpack2(hg8, h1, h3);
            uint32_t a0 = tf32_rna(fmaxf(h0, 0.f));
            uint32_t a1 = tf32_rna(fmaxf(h1, 0.f));
            uint32_t a2 = tf32_rna(fmaxf(h2, 0.f));
            uint32_t a3 = tf32_rna(fmaxf(h3, 0.f));

            // t = h @ pw1 + pb1
            float d0 = e0.x, d1 = e0.y, d2 = e0.x, d3 = e0.y;
            mma_tf32(d0, d1, d2, d3, a0, a1, a2, a3, bf0.x, bf0.y);
            float f0 = e1.x, f1 = e1.y, f2 = e1.x, f3 = e1.y;
            mma_tf32(f0, f1, f2, f3, a0, a1, a2, a3, bf1.x, bf1.y);

            // out += relu(t) . pw2
            outv[2*sub]   = fmaf(fmaxf(d0, 0.f), e0.z, outv[2*sub]);
            outv[2*sub]   = fmaf(fmaxf(d1, 0.f), e0.w, outv[2*sub]);
            outv[2*sub]   = fmaf(fmaxf(f0, 0.f), e1.z, outv[2*sub]);
            outv[2*sub]   = fmaf(fmaxf(f1, 0.f), e1.w, outv[2*sub]);
            outv[2*sub+1] = fmaf(fmaxf(d2, 0.f), e0.z, outv[2*sub+1]);
            outv[2*sub+1] = fmaf(fmaxf(d3, 0.f), e0.w, outv[2*sub+1]);
            outv[2*sub+1] = fmaf(fmaxf(f2, 0.f), e1.z, outv[2*sub+1]);
            outv[2*sub+1] = fmaf(fmaxf(f3, 0.f), e1.w, outv[2*sub+1]);
        }
    }

    // reduce over the 4 col-partition threads of each row group
    #pragma unroll
    for (int i = 0; i < 8; ++i) {
        outv[i] += __shfl_xor_sync(0xffffffffu, outv[i], 1);
        outv[i] += __shfl_xor_sync(0xffffffffu, outv[i], 2);
    }
    if (c == 0) {
        #pragma unroll
        for (int sub = 0; sub < 4; ++sub) {
            g_partial[(size_t)chunk * BATCH + g0 + sbase + sub * 16 + g]     = outv[2*sub];
            g_partial[(size_t)chunk * BATCH + g0 + sbase + sub * 16 + g + 8] = outv[2*sub + 1];
        }
    }
}

// ---------------------------------------------------------------------------
// Kernel 3: deterministic final reduction over 34 partial slices.
// ---------------------------------------------------------------------------
__global__ __launch_bounds__(128)
void reduce_kernel(float* __restrict__ out)
{
    const int b = blockIdx.x * 128 + threadIdx.x;
    float s = 0.0f;
    #pragma unroll
    for (int c = 0; c < PK_NCHUNK + 2; ++c)
        s += g_partial[c * BATCH + b];
    out[b] = s;
}

// ---------------------------------------------------------------------------
extern "C" void kernel_launch(void* const* d_in, const int* in_sizes, int n_in,
                              void* d_out, int out_size)
{
    const float* x   = (const float*)d_in[0];
    const float* z   = (const float*)d_in[1];
    const float* xw1 = (const float*)d_in[2];
    const float* xb1 = (const float*)d_in[3];
    const float* xw2 = (const float*)d_in[4];
    const float* xb2 = (const float*)d_in[5];
    const float* xw3 = (const float*)d_in[6];
    const float* xb3 = (const float*)d_in[7];
    const float* zw1 = (const float*)d_in[8];
    const float* zb1 = (const float*)d_in[9];
    const float* zw2 = (const float*)d_in[10];
    const float* zb2 = (const float*)d_in[11];
    const float* zw3 = (const float*)d_in[12];
    const float* zb3 = (const float*)d_in[13];
    const float* xzw = (const float*)d_in[14];
    const float* xzb = (const float*)d_in[15];
    const float* pw1 = (const float*)d_in[16];
    const float* pb1 = (const float*)d_in[17];
    const float* pw2 = (const float*)d_in[18];
    float* out = (float*)d_out;

    static cudaStream_t s2 = nullptr;
    static cudaEvent_t  e_fork = nullptr, e_join = nullptr;
    if (s2 == nullptr) {
        cudaStreamCreateWithFlags(&s2, cudaStreamNonBlocking);
        cudaEventCreateWithFlags(&e_fork, cudaEventDisableTiming);
        cudaEventCreateWithFlags(&e_join, cudaEventDisableTiming);
    }

    const size_t smem_mlp = 22848u * sizeof(float);   // 91392 B
    cudaFuncSetAttribute(mlp_kernel, cudaFuncAttributeMaxDynamicSharedMemorySize, (int)smem_mlp);

    // fork: mlp on side stream
    cudaEventRecord(e_fork, 0);
    cudaStreamWaitEvent(s2, e_fork, 0);
    mlp_kernel<<<dim3(MK_NTILE, 2), 256, smem_mlp, s2>>>(x, z,
        xw1, xb1, xw2, xb2, xw3, xb3,
        zw1, zb1, zw2, zb2, zw3, zb3);
    cudaEventRecord(e_join, s2);

    transpose_kernel<<<BATCH / 64, 256>>>(x, z);
    pair_kernel<<<dim3(16, 32), 256>>>(xzw, xzb, pw1, pb1, pw2);

    cudaStreamWaitEvent(0, e_join, 0);
    reduce_kernel<<<BATCH / 128, 128>>>(out);
}

// round 8
// speedup vs baseline: 1.3226x; 1.0033x over previous
#include <cuda_runtime.h>
#include <cuda_bf16.h>
#include <cstdint>

// Problem constants
#define BATCH   8192
#define R_DIM   8
#define PH_DIM  16
#define PAIRS   1024
#define OUT_U   8192   // PAIRS * R

#define PK_NCHUNK 32         // 32 pair chunks of 32 pairs
#define MK_TILE   64
#define MK_NTILE  (BATCH / MK_TILE)

// Deterministic partial buffer: 32 interaction chunks + X + Z
__device__ float g_partial[(PK_NCHUNK + 2) * BATCH];
// Transposed inputs: [32][8192]
__device__ float g_xT[32 * BATCH];
__device__ float g_zT[32 * BATCH];

typedef unsigned long long ull;

// ---- packed f32x2 helpers ---------------------------------------------------
__device__ __forceinline__ ull pack2(float lo, float hi) {
    ull r;
    asm("mov.b64 %0, {%1, %2};" : "=l"(r) : "f"(lo), "f"(hi));
    return r;
}
__device__ __forceinline__ void unpack2(ull v, float& lo, float& hi) {
    asm("mov.b64 {%0, %1}, %2;" : "=f"(lo), "=f"(hi) : "l"(v));
}
__device__ __forceinline__ ull fma2(ull a, ull b, ull c) {
    ull d;
    asm("fma.rn.f32x2 %0, %1, %2, %3;" : "=l"(d) : "l"(a), "l"(b), "l"(c));
    return d;
}
__device__ __forceinline__ uint32_t tf32_rna(float v) {
    uint32_t u;
    asm("cvt.rna.tf32.f32 %0, %1;" : "=r"(u) : "f"(v));
    return u;
}
// mma.sync m16n8k8 tf32: D = A(16x8,row) * B(8x8,col) + C  (fp32 accum)
__device__ __forceinline__ void mma_tf32(float& d0, float& d1, float& d2, float& d3,
                                         uint32_t a0, uint32_t a1, uint32_t a2, uint32_t a3,
                                         uint32_t b0, uint32_t b1) {
    asm volatile(
        "mma.sync.aligned.m16n8k8.row.col.f32.tf32.tf32.f32 "
        "{%0,%1,%2,%3}, {%4,%5,%6,%7}, {%8,%9}, {%0,%1,%2,%3};\n"
        : "+f"(d0), "+f"(d1), "+f"(d2), "+f"(d3)
        : "r"(a0), "r"(a1), "r"(a2), "r"(a3), "r"(b0), "r"(b1));
}

// ---------------------------------------------------------------------------
// Kernel 0: transpose x,z [8192][32] -> [32][8192]
// ---------------------------------------------------------------------------
__global__ __launch_bounds__(256)
void transpose_kernel(const float* __restrict__ x, const float* __restrict__ z)
{
    __shared__ float tx[64 * 33];
    __shared__ float tz[64 * 33];
    const int tid = threadIdx.x;
    const int g0  = blockIdx.x * 64;

    for (int idx = tid; idx < 64 * 32; idx += 256) {
        int s = idx >> 5, c = idx & 31;
        tx[s * 33 + c] = x[(size_t)g0 * 32 + idx];
        tz[s * 33 + c] = z[(size_t)g0 * 32 + idx];
    }
    __syncthreads();
    for (int idx = tid; idx < 64 * 32; idx += 256) {
        int c = idx >> 6, s = idx & 63;
        g_xT[(size_t)c * BATCH + g0 + s] = tx[s * 33 + c];
        g_zT[(size_t)c * BATCH + g0 + s] = tz[s * 33 + c];
    }
}

// ---------------------------------------------------------------------------
// Kernel 1: main-effect MLPs (32->128->64->1). blockIdx.y = part (x or z).
// 256 threads; proven round-6 version.
// ---------------------------------------------------------------------------
__global__ __launch_bounds__(256)
void mlp_kernel(const float* __restrict__ x, const float* __restrict__ z,
                const float* __restrict__ xw1, const float* __restrict__ xb1,
                const float* __restrict__ xw2, const float* __restrict__ xb2,
                const float* __restrict__ xw3, const float* __restrict__ xb3,
                const float* __restrict__ zw1, const float* __restrict__ zb1,
                const float* __restrict__ zw2, const float* __restrict__ zb2,
                const float* __restrict__ zw3, const float* __restrict__ zb3)
{
    extern __shared__ float sm[];
    float* in_sm = sm;                 // 64*32   = 2048
    float* h1_sm = sm + 2048;          // 64*128  = 8192
    float* w2_sm = sm + 10240;         // 128*64  = 8192
    float* h2_sm = sm + 18432;         // 64*68   = 4352
    float* w3_sm = sm + 22784;         // 64

    const int tid  = threadIdx.x;
    const int tile = blockIdx.x;
    const int part = blockIdx.y;
    const int g0   = tile * MK_TILE;

    const float* in = part ? z   : x;
    const float* w1 = part ? zw1 : xw1;
    const float* b1 = part ? zb1 : xb1;
    const float* w2 = part ? zw2 : xw2;
    const float* b2 = part ? zb2 : xb2;
    const float* w3 = part ? zw3 : xw3;
    const float* b3 = part ? zb3 : xb3;

    for (int idx = tid; idx < MK_TILE * 32; idx += 256)
        in_sm[idx] = in[(size_t)g0 * 32 + idx];
    for (int idx = tid; idx < 128 * 64; idx += 256)
        w2_sm[idx] = w2[idx];
    if (tid < 64) w3_sm[tid] = w3[tid];

    const int u    = tid & 127;        // hidden unit
    const int half = tid >> 7;         // sample half (0/1)

    float wc[32];
    #pragma unroll
    for (int l = 0; l < 32; ++l) wc[l] = w1[l * 128 + u];
    const float bc = b1[u];

    __syncthreads();

    // ---- phase 1: 4 samples in flight ----
    for (int s0 = half * 32; s0 < half * 32 + 32; s0 += 4) {
        float a0 = bc, a1 = bc, a2 = bc, a3 = bc;
        const float4* r0 = (const float4*)(in_sm + (s0 + 0) * 32);
        const float4* r1 = (const float4*)(in_sm + (s0 + 1) * 32);
        const float4* r2 = (const float4*)(in_sm + (s0 + 2) * 32);
        const float4* r3 = (const float4*)(in_sm + (s0 + 3) * 32);
        #pragma unroll
        for (int l4 = 0; l4 < 8; ++l4) {
            float4 v0 = r0[l4], v1 = r1[l4], v2 = r2[l4], v3 = r3[l4];
            float w0 = wc[l4 * 4 + 0], w1c = wc[l4 * 4 + 1];
            float w2c = wc[l4 * 4 + 2], w3c = wc[l4 * 4 + 3];
            a0 = fmaf(v0.x, w0, a0); a1 = fmaf(v1.x, w0, a1);
            a2 = fmaf(v2.x, w0, a2); a3 = fmaf(v3.x, w0, a3);
            a0 = fmaf(v0.y, w1c, a0); a1 = fmaf(v1.y, w1c, a1);
            a2 = fmaf(v2.y, w1c, a2); a3 = fmaf(v3.y, w1c, a3);
            a0 = fmaf(v0.z, w2c, a0); a1 = fmaf(v1.z, w2c, a1);
            a2 = fmaf(v2.z, w2c, a2); a3 = fmaf(v3.z, w2c, a3);
            a0 = fmaf(v0.w, w3c, a0); a1 = fmaf(v1.w, w3c, a1);
            a2 = fmaf(v2.w, w3c, a2); a3 = fmaf(v3.w, w3c, a3);
        }
        h1_sm[(s0 + 0) * 128 + u] = fmaxf(a0, 0.0f);
        h1_sm[(s0 + 1) * 128 + u] = fmaxf(a1, 0.0f);
        h1_sm[(s0 + 2) * 128 + u] = fmaxf(a2, 0.0f);
        h1_sm[(s0 + 3) * 128 + u] = fmaxf(a3, 0.0f);
    }
    __syncthreads();

    // ---- phase 2: 4 samples/thread, f32x2 ----
    {
        const int oq = tid & 15;
        const int sg = tid >> 4;
        float4 bb = ((const float4*)b2)[oq];
        ull accA[4], accB[4];
        const ull bA = pack2(bb.x, bb.y);
        const ull bB = pack2(bb.z, bb.w);
        #pragma unroll
        for (int ss = 0; ss < 4; ++ss) { accA[ss] = bA; accB[ss] = bB; }

        const float4* w24   = (const float4*)w2_sm;
        const float4* hbase = (const float4*)(h1_sm + sg * 4 * 128);

        #pragma unroll 4
        for (int l4 = 0; l4 < 32; ++l4) {
            float4 wA = w24[(l4 * 4 + 0) * 16 + oq];
            float4 wB = w24[(l4 * 4 + 1) * 16 + oq];
            float4 wC = w24[(l4 * 4 + 2) * 16 + oq];
            float4 wD = w24[(l4 * 4 + 3) * 16 + oq];
            const ulonglong2 wAp = *(const ulonglong2*)&wA;
            const ulonglong2 wBp = *(const ulonglong2*)&wB;
            const ulonglong2 wCp = *(const ulonglong2*)&wC;
            const ulonglong2 wDp = *(const ulonglong2*)&wD;
            #pragma unroll
            for (int ss = 0; ss < 4; ++ss) {
                float4 hv = hbase[ss * 32 + l4];
                ull hx = pack2(hv.x, hv.x);
                ull hy = pack2(hv.y, hv.y);
                ull hz = pack2(hv.z, hv.z);
                ull hw = pack2(hv.w, hv.w);
                accA[ss] = fma2(hx, wAp.x, accA[ss]); accB[ss] = fma2(hx, wAp.y, accB[ss]);
                accA[ss] = fma2(hy, wBp.x, accA[ss]); accB[ss] = fma2(hy, wBp.y, accB[ss]);
                accA[ss] = fma2(hz, wCp.x, accA[ss]); accB[ss] = fma2(hz, wCp.y, accB[ss]);
                accA[ss] = fma2(hw, wDp.x, accA[ss]); accB[ss] = fma2(hw, wDp.y, accB[ss]);
            }
        }
        #pragma unroll
        for (int ss = 0; ss < 4; ++ss) {
            const int s = sg * 4 + ss;
            float a0, a1, a2, a3;
            unpack2(accA[ss], a0, a1);
            unpack2(accB[ss], a2, a3);
            float4 r;
            r.x = fmaxf(a0, 0.0f); r.y = fmaxf(a1, 0.0f);
            r.z = fmaxf(a2, 0.0f); r.w = fmaxf(a3, 0.0f);
            *(float4*)(h2_sm + s * 68 + oq * 4) = r;
        }
    }
    __syncthreads();

    // ---- phase 3 ----
    {
        const int s = tid >> 2, q = tid & 3;
        const float4* hr = (const float4*)(h2_sm + s * 68 + q * 16);
        const float4* wr = (const float4*)(w3_sm + q * 16);
        float acc = 0.0f;
        #pragma unroll
        for (int i = 0; i < 4; ++i) {
            float4 h = hr[i], w = wr[i];
            acc = fmaf(h.x, w.x, acc);
            acc = fmaf(h.y, w.y, acc);
            acc = fmaf(h.z, w.z, acc);
            acc = fmaf(h.w, w.w, acc);
        }
        acc += __shfl_xor_sync(0xffffffffu, acc, 1);
        acc += __shfl_xor_sync(0xffffffffu, acc, 2);
        if (q == 0)
            g_partial[(PK_NCHUNK + part) * BATCH + g0 + s] = acc + b3[0];
    }
}

// ---------------------------------------------------------------------------
// Kernel 2: structured interaction + per-pair MLPs via tf32 mma, pairs-outer.
// grid = (16 sample tiles of 512, 32 chunks), 256 threads = 8 warps.
// Warp owns 64 samples (4 m16 subtiles). Per pair: B-frags (pw1), epilogue
// (pb1/pw2) and h-weights loaded ONCE into regs, reused across 4 subtiles.
// x pairs pre-duplicated in smem (keeps regs <= 64 for occupancy 4 -> 1 wave).
// ---------------------------------------------------------------------------
__global__ __launch_bounds__(256, 4)
void pair_kernel(const float* __restrict__ xzw, const float* __restrict__ xzb,
                 const float* __restrict__ pw1, const float* __restrict__ pb1,
                 const float* __restrict__ pw2)
{
    __shared__ __align__(16) ull   x2_sm[512];         // dup-packed x column (4KB)
    __shared__ __align__(16) float wq_sm[1024];        // [pair][c]{wx_c,wx_c4,wz_c,wz_c4,bb_c,bb_c4,0,0}
    __shared__ __align__(16) float bf_sm[4096];        // pw1 tf32 B-frags
    __shared__ __align__(16) float ep_sm[1024];        // [pair][cp]{pb,pb,pw2,pw2}

    const int tid   = threadIdx.x;
    const int tile  = blockIdx.x;    // 0..15
    const int chunk = blockIdx.y;    // 0..31
    const int g0    = tile * 512;
    const int p0    = chunk * 32;

    // ---- staging ----
    for (int idx = tid; idx < 512; idx += 256) {
        float xv = g_xT[(size_t)chunk * BATCH + g0 + idx];
        x2_sm[idx] = pack2(xv, xv);
    }
    for (int idx = tid; idx < 1024; idx += 256) {
        int pr = idx >> 5, c = (idx >> 3) & 3, e = idx & 7;
        int p  = p0 + pr;
        int j  = c + ((e & 1) << 2);
        float v = 0.f;
        if (e < 2)      v = xzw[(size_t)chunk * OUT_U + p * 8 + j];
        else if (e < 4) v = xzw[(size_t)(32 + pr) * OUT_U + p * 8 + j];
        else if (e < 6) v = xzb[p * 8 + j];
        wq_sm[idx] = v;
    }
    for (int idx = tid; idx < 4096; idx += 256) {
        int pr = idx >> 7, r = idx & 127;
        int nm = r >> 6, r2 = r & 63;
        int ln = r2 >> 1, half = r2 & 1;
        int k = (ln & 3) + (half << 2);
        int n = (ln >> 2) + (nm << 3);
        bf_sm[idx] = __uint_as_float(tf32_rna(pw1[(size_t)(p0 + pr) * 128 + k * 16 + n]));
    }
    for (int idx = tid; idx < 1024; idx += 256) {
        int pr = idx >> 5, r = idx & 31;
        int cp = r >> 2, e = r & 3;
        int col = 2 * cp + (e & 1);
        ep_sm[idx] = (e < 2) ? pb1[(p0 + pr) * 16 + col]
                             : pw2[(p0 + pr) * 16 + col];
    }
    __syncthreads();

    const int lane = tid & 31, w = tid >> 5;
    const int g = lane >> 2, c = lane & 3;
    const int sbase = w * 64;                  // warp's sample base within tile

    float outv[8];
    #pragma unroll
    for (int i = 0; i < 8; ++i) outv[i] = 0.f;

    const float* zT = g_zT + g0;

    #pragma unroll 1
    for (int pl = 0; pl < 32; ++pl) {
        // per-pair registers (reused across 4 subtiles)
        ulonglong2 wu = *(const ulonglong2*)&wq_sm[(pl * 4 + c) * 8];
        ull bbu = *(const ull*)&wq_sm[(pl * 4 + c) * 8 + 4];
        uint2 bf0 = *(const uint2*)&bf_sm[pl * 128 + lane * 2];
        uint2 bf1 = *(const uint2*)&bf_sm[pl * 128 + 64 + lane * 2];
        float4 e0 = *(const float4*)&ep_sm[(pl * 8 + c) * 4];
        float4 e1 = *(const float4*)&ep_sm[(pl * 8 + c + 4) * 4];
        const float* zcol = zT + (size_t)pl * BATCH;

        #pragma unroll
        for (int sub = 0; sub < 4; ++sub) {
            const int srow = sbase + sub * 16 + g;
            float zg  = zcol[srow];
            float zg8 = zcol[srow + 8];

            // h in A-frag layout: rows {g, g+8} x cols {c, c+4}
            ull hg  = fma2(wu.x, x2_sm[srow],     fma2(wu.y, pack2(zg,  zg),  bbu));
            ull hg8 = fma2(wu.x, x2_sm[srow + 8], fma2(wu.y, pack2(zg8, zg8), bbu));
            float h0, h2, h1, h3;
            unpack2(hg,  h0, h2);
            unpack2(hg8, h1, h3);
            uint32_t a0 = tf32_rna(fmaxf(h0, 0.f));
            uint32_t a1 = tf32_rna(fmaxf(h1, 0.f));
            uint32_t a2 = tf32_rna(fmaxf(h2, 0.f));
            uint32_t a3 = tf32_rna(fmaxf(h3, 0.f));

            // t = h @ pw1 + pb1
            float d0 = e0.x, d1 = e0.y, d2 = e0.x, d3 = e0.y;
            mma_tf32(d0, d1, d2, d3, a0, a1, a2, a3, bf0.x, bf0.y);
            float f0 = e1.x, f1 = e1.y, f2 = e1.x, f3 = e1.y;
            mma_tf32(f0, f1, f2, f3, a0, a1, a2, a3, bf1.x, bf1.y);

            // out += relu(t) . pw2
            outv[2*sub]   = fmaf(fmaxf(d0, 0.f), e0.z, outv[2*sub]);
            outv[2*sub]   = fmaf(fmaxf(d1, 0.f), e0.w, outv[2*sub]);
            outv[2*sub]   = fmaf(fmaxf(f0, 0.f), e1.z, outv[2*sub]);
            outv[2*sub]   = fmaf(fmaxf(f1, 0.f), e1.w, outv[2*sub]);
            outv[2*sub+1] = fmaf(fmaxf(d2, 0.f), e0.z, outv[2*sub+1]);
            outv[2*sub+1] = fmaf(fmaxf(d3, 0.f), e0.w, outv[2*sub+1]);
            outv[2*sub+1] = fmaf(fmaxf(f2, 0.f), e1.z, outv[2*sub+1]);
            outv[2*sub+1] = fmaf(fmaxf(f3, 0.f), e1.w, outv[2*sub+1]);
        }
    }

    // reduce over the 4 col-partition threads of each row group
    #pragma unroll
    for (int i = 0; i < 8; ++i) {
        outv[i] += __shfl_xor_sync(0xffffffffu, outv[i], 1);
        outv[i] += __shfl_xor_sync(0xffffffffu, outv[i], 2);
    }
    if (c == 0) {
        #pragma unroll
        for (int sub = 0; sub < 4; ++sub) {
            g_partial[(size_t)chunk * BATCH + g0 + sbase + sub * 16 + g]     = outv[2*sub];
            g_partial[(size_t)chunk * BATCH + g0 + sbase + sub * 16 + g + 8] = outv[2*sub + 1];
        }
    }
}

// ---------------------------------------------------------------------------
// Kernel 3: deterministic final reduction over 34 partial slices.
// ---------------------------------------------------------------------------
__global__ __launch_bounds__(128)
void reduce_kernel(float* __restrict__ out)
{
    const int b = blockIdx.x * 128 + threadIdx.x;
    float s = 0.0f;
    #pragma unroll
    for (int c = 0; c < PK_NCHUNK + 2; ++c)
        s += g_partial[c * BATCH + b];
    out[b] = s;
}

// ---------------------------------------------------------------------------
extern "C" void kernel_launch(void* const* d_in, const int* in_sizes, int n_in,
                              void* d_out, int out_size)
{
    const float* x   = (const float*)d_in[0];
    const float* z   = (const float*)d_in[1];
    const float* xw1 = (const float*)d_in[2];
    const float* xb1 = (const float*)d_in[3];
    const float* xw2 = (const float*)d_in[4];
    const float* xb2 = (const float*)d_in[5];
    const float* xw3 = (const float*)d_in[6];
    const float* xb3 = (const float*)d_in[7];
    const float* zw1 = (const float*)d_in[8];
    const float* zb1 = (const float*)d_in[9];
    const float* zw2 = (const float*)d_in[10];
    const float* zb2 = (const float*)d_in[11];
    const float* zw3 = (const float*)d_in[12];
    const float* zb3 = (const float*)d_in[13];
    const float* xzw = (const float*)d_in[14];
    const float* xzb = (const float*)d_in[15];
    const float* pw1 = (const float*)d_in[16];
    const float* pb1 = (const float*)d_in[17];
    const float* pw2 = (const float*)d_in[18];
    float* out = (float*)d_out;

    static cudaStream_t s2 = nullptr;
    static cudaEvent_t  e_fork = nullptr, e_join = nullptr;
    if (s2 == nullptr) {
        cudaStreamCreateWithFlags(&s2, cudaStreamNonBlocking);
        cudaEventCreateWithFlags(&e_fork, cudaEventDisableTiming);
        cudaEventCreateWithFlags(&e_join, cudaEventDisableTiming);
        // allow 4 CTAs x 28KB static smem per SM
        cudaFuncSetAttribute(pair_kernel,
            cudaFuncAttributePreferredSharedMemoryCarveout, 100);
    }

    const size_t smem_mlp = 22848u * sizeof(float);   // 91392 B
    cudaFuncSetAttribute(mlp_kernel, cudaFuncAttributeMaxDynamicSharedMemorySize, (int)smem_mlp);

    // fork: mlp on side stream
    cudaEventRecord(e_fork, 0);
    cudaStreamWaitEvent(s2, e_fork, 0);
    mlp_kernel<<<dim3(MK_NTILE, 2), 256, smem_mlp, s2>>>(x, z,
        xw1, xb1, xw2, xb2, xw3, xb3,
        zw1, zb1, zw2, zb2, zw3, zb3);
    cudaEventRecord(e_join, s2);

    transpose_kernel<<<BATCH / 64, 256>>>(x, z);
    pair_kernel<<<dim3(16, 32), 256>>>(xzw, xzb, pw1, pb1, pw2);

    cudaStreamWaitEvent(0, e_join, 0);
    reduce_kernel<<<BATCH / 128, 128>>>(out);
}

// round 9
// speedup vs baseline: 1.4422x; 1.0905x over previous
#include <cuda_runtime.h>
#include <cuda_bf16.h>
#include <cstdint>

// Problem constants
#define BATCH   8192
#define R_DIM   8
#define PH_DIM  16
#define PAIRS   1024
#define OUT_U   8192   // PAIRS * R

#define PK_NCHUNK 32         // 32 pair chunks of 32 pairs
#define MK_TILE   64
#define MK_NTILE  (BATCH / MK_TILE)

// Deterministic partial buffer: 32 interaction chunks + X + Z
__device__ float g_partial[(PK_NCHUNK + 2) * BATCH];
// Transposed inputs: [32][8192]
__device__ float g_xT[32 * BATCH];
__device__ float g_zT[32 * BATCH];

typedef unsigned long long ull;

// ---- packed f32x2 helpers ---------------------------------------------------
__device__ __forceinline__ ull pack2(float lo, float hi) {
    ull r;
    asm("mov.b64 %0, {%1, %2};" : "=l"(r) : "f"(lo), "f"(hi));
    return r;
}
__device__ __forceinline__ void unpack2(ull v, float& lo, float& hi) {
    asm("mov.b64 {%0, %1}, %2;" : "=f"(lo), "=f"(hi) : "l"(v));
}
__device__ __forceinline__ ull fma2(ull a, ull b, ull c) {
    ull d;
    asm("fma.rn.f32x2 %0, %1, %2, %3;" : "=l"(d) : "l"(a), "l"(b), "l"(c));
    return d;
}
__device__ __forceinline__ uint32_t tf32_rna(float v) {
    uint32_t u;
    asm("cvt.rna.tf32.f32 %0, %1;" : "=r"(u) : "f"(v));
    return u;
}
// mma.sync m16n8k8 tf32: D = A(16x8,row) * B(8x8,col) + C  (fp32 accum)
__device__ __forceinline__ void mma_tf32(float& d0, float& d1, float& d2, float& d3,
                                         uint32_t a0, uint32_t a1, uint32_t a2, uint32_t a3,
                                         uint32_t b0, uint32_t b1) {
    asm volatile(
        "mma.sync.aligned.m16n8k8.row.col.f32.tf32.tf32.f32 "
        "{%0,%1,%2,%3}, {%4,%5,%6,%7}, {%8,%9}, {%0,%1,%2,%3};\n"
        : "+f"(d0), "+f"(d1), "+f"(d2), "+f"(d3)
        : "r"(a0), "r"(a1), "r"(a2), "r"(a3), "r"(b0), "r"(b1));
}

// ---------------------------------------------------------------------------
// Kernel 0: transpose x,z [8192][32] -> [32][8192]
// ---------------------------------------------------------------------------
__global__ __launch_bounds__(256)
void transpose_kernel(const float* __restrict__ x, const float* __restrict__ z)
{
    __shared__ float tx[64 * 33];
    __shared__ float tz[64 * 33];
    const int tid = threadIdx.x;
    const int g0  = blockIdx.x * 64;

    for (int idx = tid; idx < 64 * 32; idx += 256) {
        int s = idx >> 5, c = idx & 31;
        tx[s * 33 + c] = x[(size_t)g0 * 32 + idx];
        tz[s * 33 + c] = z[(size_t)g0 * 32 + idx];
    }
    __syncthreads();
    for (int idx = tid; idx < 64 * 32; idx += 256) {
        int c = idx >> 6, s = idx & 63;
        g_xT[(size_t)c * BATCH + g0 + s] = tx[s * 33 + c];
        g_zT[(size_t)c * BATCH + g0 + s] = tz[s * 33 + c];
    }
}

// ---------------------------------------------------------------------------
// Kernel 1: main-effect MLPs (32->128->64->1). blockIdx.y = part (x or z).
// 256 threads; proven round-6 version.
// ---------------------------------------------------------------------------
__global__ __launch_bounds__(256)
void mlp_kernel(const float* __restrict__ x, const float* __restrict__ z,
                const float* __restrict__ xw1, const float* __restrict__ xb1,
                const float* __restrict__ xw2, const float* __restrict__ xb2,
                const float* __restrict__ xw3, const float* __restrict__ xb3,
                const float* __restrict__ zw1, const float* __restrict__ zb1,
                const float* __restrict__ zw2, const float* __restrict__ zb2,
                const float* __restrict__ zw3, const float* __restrict__ zb3)
{
    extern __shared__ float sm[];
    float* in_sm = sm;                 // 64*32   = 2048
    float* h1_sm = sm + 2048;          // 64*128  = 8192
    float* w2_sm = sm + 10240;         // 128*64  = 8192
    float* h2_sm = sm + 18432;         // 64*68   = 4352
    float* w3_sm = sm + 22784;         // 64

    const int tid  = threadIdx.x;
    const int tile = blockIdx.x;
    const int part = blockIdx.y;
    const int g0   = tile * MK_TILE;

    const float* in = part ? z   : x;
    const float* w1 = part ? zw1 : xw1;
    const float* b1 = part ? zb1 : xb1;
    const float* w2 = part ? zw2 : xw2;
    const float* b2 = part ? zb2 : xb2;
    const float* w3 = part ? zw3 : xw3;
    const float* b3 = part ? zb3 : xb3;

    for (int idx = tid; idx < MK_TILE * 32; idx += 256)
        in_sm[idx] = in[(size_t)g0 * 32 + idx];
    for (int idx = tid; idx < 128 * 64; idx += 256)
        w2_sm[idx] = w2[idx];
    if (tid < 64) w3_sm[tid] = w3[tid];

    const int u    = tid & 127;        // hidden unit
    const int half = tid >> 7;         // sample half (0/1)

    float wc[32];
    #pragma unroll
    for (int l = 0; l < 32; ++l) wc[l] = w1[l * 128 + u];
    const float bc = b1[u];

    __syncthreads();

    // ---- phase 1: 4 samples in flight ----
    for (int s0 = half * 32; s0 < half * 32 + 32; s0 += 4) {
        float a0 = bc, a1 = bc, a2 = bc, a3 = bc;
        const float4* r0 = (const float4*)(in_sm + (s0 + 0) * 32);
        const float4* r1 = (const float4*)(in_sm + (s0 + 1) * 32);
        const float4* r2 = (const float4*)(in_sm + (s0 + 2) * 32);
        const float4* r3 = (const float4*)(in_sm + (s0 + 3) * 32);
        #pragma unroll
        for (int l4 = 0; l4 < 8; ++l4) {
            float4 v0 = r0[l4], v1 = r1[l4], v2 = r2[l4], v3 = r3[l4];
            float w0 = wc[l4 * 4 + 0], w1c = wc[l4 * 4 + 1];
            float w2c = wc[l4 * 4 + 2], w3c = wc[l4 * 4 + 3];
            a0 = fmaf(v0.x, w0, a0); a1 = fmaf(v1.x, w0, a1);
            a2 = fmaf(v2.x, w0, a2); a3 = fmaf(v3.x, w0, a3);
            a0 = fmaf(v0.y, w1c, a0); a1 = fmaf(v1.y, w1c, a1);
            a2 = fmaf(v2.y, w1c, a2); a3 = fmaf(v3.y, w1c, a3);
            a0 = fmaf(v0.z, w2c, a0); a1 = fmaf(v1.z, w2c, a1);
            a2 = fmaf(v2.z, w2c, a2); a3 = fmaf(v3.z, w2c, a3);
            a0 = fmaf(v0.w, w3c, a0); a1 = fmaf(v1.w, w3c, a1);
            a2 = fmaf(v2.w, w3c, a2); a3 = fmaf(v3.w, w3c, a3);
        }
        h1_sm[(s0 + 0) * 128 + u] = fmaxf(a0, 0.0f);
        h1_sm[(s0 + 1) * 128 + u] = fmaxf(a1, 0.0f);
        h1_sm[(s0 + 2) * 128 + u] = fmaxf(a2, 0.0f);
        h1_sm[(s0 + 3) * 128 + u] = fmaxf(a3, 0.0f);
    }
    __syncthreads();

    // ---- phase 2: 4 samples/thread, f32x2 ----
    {
        const int oq = tid & 15;
        const int sg = tid >> 4;
        float4 bb = ((const float4*)b2)[oq];
        ull accA[4], accB[4];
        const ull bA = pack2(bb.x, bb.y);
        const ull bB = pack2(bb.z, bb.w);
        #pragma unroll
        for (int ss = 0; ss < 4; ++ss) { accA[ss] = bA; accB[ss] = bB; }

        const float4* w24   = (const float4*)w2_sm;
        const float4* hbase = (const float4*)(h1_sm + sg * 4 * 128);

        #pragma unroll 4
        for (int l4 = 0; l4 < 32; ++l4) {
            float4 wA = w24[(l4 * 4 + 0) * 16 + oq];
            float4 wB = w24[(l4 * 4 + 1) * 16 + oq];
            float4 wC = w24[(l4 * 4 + 2) * 16 + oq];
            float4 wD = w24[(l4 * 4 + 3) * 16 + oq];
            const ulonglong2 wAp = *(const ulonglong2*)&wA;
            const ulonglong2 wBp = *(const ulonglong2*)&wB;
            const ulonglong2 wCp = *(const ulonglong2*)&wC;
            const ulonglong2 wDp = *(const ulonglong2*)&wD;
            #pragma unroll
            for (int ss = 0; ss < 4; ++ss) {
                float4 hv = hbase[ss * 32 + l4];
                ull hx = pack2(hv.x, hv.x);
                ull hy = pack2(hv.y, hv.y);
                ull hz = pack2(hv.z, hv.z);
                ull hw = pack2(hv.w, hv.w);
                accA[ss] = fma2(hx, wAp.x, accA[ss]); accB[ss] = fma2(hx, wAp.y, accB[ss]);
                accA[ss] = fma2(hy, wBp.x, accA[ss]); accB[ss] = fma2(hy, wBp.y, accB[ss]);
                accA[ss] = fma2(hz, wCp.x, accA[ss]); accB[ss] = fma2(hz, wCp.y, accB[ss]);
                accA[ss] = fma2(hw, wDp.x, accA[ss]); accB[ss] = fma2(hw, wDp.y, accB[ss]);
            }
        }
        #pragma unroll
        for (int ss = 0; ss < 4; ++ss) {
            const int s = sg * 4 + ss;
            float a0, a1, a2, a3;
            unpack2(accA[ss], a0, a1);
            unpack2(accB[ss], a2, a3);
            float4 r;
            r.x = fmaxf(a0, 0.0f); r.y = fmaxf(a1, 0.0f);
            r.z = fmaxf(a2, 0.0f); r.w = fmaxf(a3, 0.0f);
            *(float4*)(h2_sm + s * 68 + oq * 4) = r;
        }
    }
    __syncthreads();

    // ---- phase 3 ----
    {
        const int s = tid >> 2, q = tid & 3;
        const float4* hr = (const float4*)(h2_sm + s * 68 + q * 16);
        const float4* wr = (const float4*)(w3_sm + q * 16);
        float acc = 0.0f;
        #pragma unroll
        for (int i = 0; i < 4; ++i) {
            float4 h = hr[i], w = wr[i];
            acc = fmaf(h.x, w.x, acc);
            acc = fmaf(h.y, w.y, acc);
            acc = fmaf(h.z, w.z, acc);
            acc = fmaf(h.w, w.w, acc);
        }
        acc += __shfl_xor_sync(0xffffffffu, acc, 1);
        acc += __shfl_xor_sync(0xffffffffu, acc, 2);
        if (q == 0)
            g_partial[(PK_NCHUNK + part) * BATCH + g0 + s] = acc + b3[0];
    }
}

// ---------------------------------------------------------------------------
// Kernel 2: structured interaction + per-pair MLPs via tf32 mma, pairs-outer.
// grid = (32 sample tiles of 256, 32 chunks) = 1024 CTAs, 128 threads = 4 warps.
// Warp owns 64 samples (4 m16 subtiles). Per pair: B-frags (pw1), epilogue
// (pb1/pw2) and h-weights loaded ONCE into regs, reused across 4 subtiles.
// Smaller work quantum -> makespan 7 half-quanta (3.5W) instead of 4W.
// A-fragments feed raw fp32 bits (tf32 layout; HW ignores low mantissa).
// ---------------------------------------------------------------------------
__global__ __launch_bounds__(128, 6)
void pair_kernel(const float* __restrict__ xzw, const float* __restrict__ xzb,
                 const float* __restrict__ pw1, const float* __restrict__ pb1,
                 const float* __restrict__ pw2)
{
    __shared__ __align__(16) ull   x2_sm[256];         // dup-packed x column (2KB)
    __shared__ __align__(16) float wq_sm[1024];        // [pair][c]{wx_c,wx_c4,wz_c,wz_c4,bb_c,bb_c4,0,0}
    __shared__ __align__(16) float bf_sm[4096];        // pw1 tf32 B-frags
    __shared__ __align__(16) float ep_sm[1024];        // [pair][cp]{pb,pb,pw2,pw2}

    const int tid   = threadIdx.x;
    const int tile  = blockIdx.x;    // 0..31
    const int chunk = blockIdx.y;    // 0..31
    const int g0    = tile * 256;
    const int p0    = chunk * 32;

    // ---- staging ----
    for (int idx = tid; idx < 256; idx += 128) {
        float xv = g_xT[(size_t)chunk * BATCH + g0 + idx];
        x2_sm[idx] = pack2(xv, xv);
    }
    for (int idx = tid; idx < 1024; idx += 128) {
        int pr = idx >> 5, c = (idx >> 3) & 3, e = idx & 7;
        int p  = p0 + pr;
        int j  = c + ((e & 1) << 2);
        float v = 0.f;
        if (e < 2)      v = xzw[(size_t)chunk * OUT_U + p * 8 + j];
        else if (e < 4) v = xzw[(size_t)(32 + pr) * OUT_U + p * 8 + j];
        else if (e < 6) v = xzb[p * 8 + j];
        wq_sm[idx] = v;
    }
    for (int idx = tid; idx < 4096; idx += 128) {
        int pr = idx >> 7, r = idx & 127;
        int nm = r >> 6, r2 = r & 63;
        int ln = r2 >> 1, half = r2 & 1;
        int k = (ln & 3) + (half << 2);
        int n = (ln >> 2) + (nm << 3);
        bf_sm[idx] = __uint_as_float(tf32_rna(pw1[(size_t)(p0 + pr) * 128 + k * 16 + n]));
    }
    for (int idx = tid; idx < 1024; idx += 128) {
        int pr = idx >> 5, r = idx & 31;
        int cp = r >> 2, e = r & 3;
        int col = 2 * cp + (e & 1);
        ep_sm[idx] = (e < 2) ? pb1[(p0 + pr) * 16 + col]
                             : pw2[(p0 + pr) * 16 + col];
    }
    __syncthreads();

    const int lane = tid & 31, w = tid >> 5;   // w 0..3
    const int g = lane >> 2, c = lane & 3;
    const int sbase = w * 64;                  // warp's sample base within tile

    float outv[8];
    #pragma unroll
    for (int i = 0; i < 8; ++i) outv[i] = 0.f;

    const float* zT = g_zT + g0;

    #pragma unroll 1
    for (int pl = 0; pl < 32; ++pl) {
        // per-pair registers (reused across 4 subtiles)
        ulonglong2 wu = *(const ulonglong2*)&wq_sm[(pl * 4 + c) * 8];
        ull bbu = *(const ull*)&wq_sm[(pl * 4 + c) * 8 + 4];
        uint2 bf0 = *(const uint2*)&bf_sm[pl * 128 + lane * 2];
        uint2 bf1 = *(const uint2*)&bf_sm[pl * 128 + 64 + lane * 2];
        float4 e0 = *(const float4*)&ep_sm[(pl * 8 + c) * 4];
        float4 e1 = *(const float4*)&ep_sm[(pl * 8 + c + 4) * 4];
        const float* zcol = zT + (size_t)pl * BATCH;

        #pragma unroll
        for (int sub = 0; sub < 4; ++sub) {
            const int srow = sbase + sub * 16 + g;
            float zg  = zcol[srow];
            float zg8 = zcol[srow + 8];

            // h in A-frag layout: rows {g, g+8} x cols {c, c+4}
            ull hg  = fma2(wu.x, x2_sm[srow],     fma2(wu.y, pack2(zg,  zg),  bbu));
            ull hg8 = fma2(wu.x, x2_sm[srow + 8], fma2(wu.y, pack2(zg8, zg8), bbu));
            float h0, h2, h1, h3;
            unpack2(hg,  h0, h2);
            unpack2(hg8, h1, h3);
            // raw fp32 bits: tf32 shares fp32 layout; MMA ignores low mantissa
            uint32_t a0 = __float_as_uint(fmaxf(h0, 0.f));
            uint32_t a1 = __float_as_uint(fmaxf(h1, 0.f));
            uint32_t a2 = __float_as_uint(fmaxf(h2, 0.f));
            uint32_t a3 = __float_as_uint(fmaxf(h3, 0.f));

            // t = h @ pw1 + pb1
            float d0 = e0.x, d1 = e0.y, d2 = e0.x, d3 = e0.y;
            mma_tf32(d0, d1, d2, d3, a0, a1, a2, a3, bf0.x, bf0.y);
            float f0 = e1.x, f1 = e1.y, f2 = e1.x, f3 = e1.y;
            mma_tf32(f0, f1, f2, f3, a0, a1, a2, a3, bf1.x, bf1.y);

            // out += relu(t) . pw2
            outv[2*sub]   = fmaf(fmaxf(d0, 0.f), e0.z, outv[2*sub]);
            outv[2*sub]   = fmaf(fmaxf(d1, 0.f), e0.w, outv[2*sub]);
            outv[2*sub]   = fmaf(fmaxf(f0, 0.f), e1.z, outv[2*sub]);
            outv[2*sub]   = fmaf(fmaxf(f1, 0.f), e1.w, outv[2*sub]);
            outv[2*sub+1] = fmaf(fmaxf(d2, 0.f), e0.z, outv[2*sub+1]);
            outv[2*sub+1] = fmaf(fmaxf(d3, 0.f), e0.w, outv[2*sub+1]);
            outv[2*sub+1] = fmaf(fmaxf(f2, 0.f), e1.z, outv[2*sub+1]);
            outv[2*sub+1] = fmaf(fmaxf(f3, 0.f), e1.w, outv[2*sub+1]);
        }
    }

    // reduce over the 4 col-partition threads of each row group
    #pragma unroll
    for (int i = 0; i < 8; ++i) {
        outv[i] += __shfl_xor_sync(0xffffffffu, outv[i], 1);
        outv[i] += __shfl_xor_sync(0xffffffffu, outv[i], 2);
    }
    if (c == 0) {
        #pragma unroll
        for (int sub = 0; sub < 4; ++sub) {
            g_partial[(size_t)chunk * BATCH + g0 + sbase + sub * 16 + g]     = outv[2*sub];
            g_partial[(size_t)chunk * BATCH + g0 + sbase + sub * 16 + g + 8] = outv[2*sub + 1];
        }
    }
}

// ---------------------------------------------------------------------------
// Kernel 3: deterministic final reduction over 34 partial slices.
// 256 threads: two 17-slice halves per output, combined via smem.
// ---------------------------------------------------------------------------
__global__ __launch_bounds__(256)
void reduce_kernel(float* __restrict__ out)
{
    __shared__ float red[256];
    const int t = threadIdx.x;
    const int b = blockIdx.x * 128 + (t & 127);
    const int half = t >> 7;
    float s = 0.0f;
    #pragma unroll
    for (int c = 0; c < 17; ++c)
        s += g_partial[(half * 17 + c) * BATCH + b];
    red[t] = s;
    __syncthreads();
    if (half == 0)
        out[b] = red[t] + red[t + 128];
}

// ---------------------------------------------------------------------------
extern "C" void kernel_launch(void* const* d_in, const int* in_sizes, int n_in,
                              void* d_out, int out_size)
{
    const float* x   = (const float*)d_in[0];
    const float* z   = (const float*)d_in[1];
    const float* xw1 = (const float*)d_in[2];
    const float* xb1 = (const float*)d_in[3];
    const float* xw2 = (const float*)d_in[4];
    const float* xb2 = (const float*)d_in[5];
    const float* xw3 = (const float*)d_in[6];
    const float* xb3 = (const float*)d_in[7];
    const float* zw1 = (const float*)d_in[8];
    const float* zb1 = (const float*)d_in[9];
    const float* zw2 = (const float*)d_in[10];
    const float* zb2 = (const float*)d_in[11];
    const float* zw3 = (const float*)d_in[12];
    const float* zb3 = (const float*)d_in[13];
    const float* xzw = (const float*)d_in[14];
    const float* xzb = (const float*)d_in[15];
    const float* pw1 = (const float*)d_in[16];
    const float* pb1 = (const float*)d_in[17];
    const float* pw2 = (const float*)d_in[18];
    float* out = (float*)d_out;

    static cudaStream_t s2 = nullptr;
    static cudaEvent_t  e_fork = nullptr, e_join = nullptr;
    if (s2 == nullptr) {
        cudaStreamCreateWithFlags(&s2, cudaStreamNonBlocking);
        cudaEventCreateWithFlags(&e_fork, cudaEventDisableTiming);
        cudaEventCreateWithFlags(&e_join, cudaEventDisableTiming);
        cudaFuncSetAttribute(pair_kernel,
            cudaFuncAttributePreferredSharedMemoryCarveout, 100);
    }

    const size_t smem_mlp = 22848u * sizeof(float);   // 91392 B
    cudaFuncSetAttribute(mlp_kernel, cudaFuncAttributeMaxDynamicSharedMemorySize, (int)smem_mlp);

    // fork: mlp on side stream
    cudaEventRecord(e_fork, 0);
    cudaStreamWaitEvent(s2, e_fork, 0);
    mlp_kernel<<<dim3(MK_NTILE, 2), 256, smem_mlp, s2>>>(x, z,
        xw1, xb1, xw2, xb2, xw3, xb3,
        zw1, zb1, zw2, zb2, zw3, zb3);
    cudaEventRecord(e_join, s2);

    transpose_kernel<<<BATCH / 64, 256>>>(x, z);
    pair_kernel<<<dim3(32, 32), 128>>>(xzw, xzb, pw1, pb1, pw2);

    cudaStreamWaitEvent(0, e_join, 0);
    reduce_kernel<<<BATCH / 128, 256>>>(out);
}